// round 1
// baseline (speedup 1.0000x reference)
#include <cuda_runtime.h>

// Problem constants
#define B_ 2
#define S_ 2048
#define D_ 1024
#define H_ 16
#define HD_ 64

// Scratch (allocation-free contract): Q,K,V projections and attention context
__device__ float g_q[(size_t)B_ * S_ * D_];
__device__ float g_k[(size_t)B_ * S_ * D_];
__device__ float g_v[(size_t)B_ * S_ * D_];
__device__ float g_o[(size_t)B_ * S_ * D_];

// Generic batched fp32 GEMM, 64x64 tile, 4x4 per thread, BK=16.
// C[m,n] = scale * sum_k A[m,k] * B[k,n]  (+ bias[n])
// TRANSB: B is [N,K] row-major (used for Q*K^T).
// Per-z offsets: z -> (zo = z / zdiv, zi = z % zdiv); ptr += zo*s?1 + zi*s?2.
template <bool TRANSB, bool HASBIAS>
__global__ __launch_bounds__(256) void gemm64(
    const float* __restrict__ Ag, const float* __restrict__ Bg,
    const float* __restrict__ bias, float* __restrict__ Cg,
    int K, int lda, int ldb, int ldc, int zdiv,
    long long sA1, long long sA2,
    long long sB1, long long sB2,
    long long sC1, long long sC2,
    float scale)
{
    constexpr int BPAD = TRANSB ? 1 : 0;   // kill store bank conflicts on transposed fill
    __shared__ float As[16][64];           // k-major: As[k][m]
    __shared__ float Bs[16][64 + BPAD];    // Bs[k][n]

    const int z  = blockIdx.z;
    const int zo = z / zdiv;
    const int zi = z - zo * zdiv;
    const float* A  = Ag + zo * sA1 + zi * sA2;
    const float* Bm = Bg + zo * sB1 + zi * sB2;
    float*       C  = Cg + zo * sC1 + zi * sC2;

    const int tid = threadIdx.x;
    const int tr  = tid >> 4;    // 0..15
    const int tc  = tid & 15;    // 0..15
    const int row0 = blockIdx.y * 64;
    const int col0 = blockIdx.x * 64;

    float acc[4][4];
#pragma unroll
    for (int i = 0; i < 4; i++)
#pragma unroll
        for (int j = 0; j < 4; j++) acc[i][j] = 0.0f;

    for (int k0 = 0; k0 < K; k0 += 16) {
        // A tile 64x16 -> As[k][m], coalesced 16-float rows
#pragma unroll
        for (int l = 0; l < 4; l++) {
            int idx = tid + l * 256;          // 0..1023
            int m = idx >> 4, kk = idx & 15;
            As[kk][m] = A[(long long)(row0 + m) * lda + (k0 + kk)];
        }
        if (TRANSB) {
            // B is [N,K]: read 16 consecutive k per n-row
#pragma unroll
            for (int l = 0; l < 4; l++) {
                int idx = tid + l * 256;
                int n = idx >> 4, kk = idx & 15;
                Bs[kk][n] = Bm[(long long)(col0 + n) * ldb + (k0 + kk)];
            }
        } else {
            // B is [K,N]: fully coalesced 64-float rows
#pragma unroll
            for (int l = 0; l < 4; l++) {
                int idx = tid + l * 256;
                int kk = idx >> 6, n = idx & 63;
                Bs[kk][n] = Bm[(long long)(k0 + kk) * ldb + (col0 + n)];
            }
        }
        __syncthreads();

#pragma unroll
        for (int kk = 0; kk < 16; kk++) {
            float a[4], b[4];
#pragma unroll
            for (int i = 0; i < 4; i++) a[i] = As[kk][tr * 4 + i];
#pragma unroll
            for (int j = 0; j < 4; j++) b[j] = Bs[kk][tc * 4 + j];
#pragma unroll
            for (int i = 0; i < 4; i++)
#pragma unroll
                for (int j = 0; j < 4; j++) acc[i][j] += a[i] * b[j];
        }
        __syncthreads();
    }

#pragma unroll
    for (int i = 0; i < 4; i++) {
        int m = row0 + tr * 4 + i;
#pragma unroll
        for (int j = 0; j < 4; j++) {
            int n = col0 + tc * 4 + j;
            float v = acc[i][j] * scale;
            if (HASBIAS) v += bias[n];
            C[(long long)m * ldc + n] = v;
        }
    }
}

// Row-wise softmax over S_=2048 elements, one block per row, in place.
__global__ __launch_bounds__(256) void softmax_rows(float* __restrict__ attn)
{
    __shared__ float buf[S_];
    __shared__ float red[256];
    const long long row = blockIdx.x;
    float* p = attn + row * (long long)S_;
    const int tid = threadIdx.x;

    float m = -1e30f;
    for (int i = tid; i < S_; i += 256) {
        float x = p[i];
        buf[i] = x;
        m = fmaxf(m, x);
    }
    red[tid] = m;
    __syncthreads();
#pragma unroll
    for (int s = 128; s > 0; s >>= 1) {
        if (tid < s) red[tid] = fmaxf(red[tid], red[tid + s]);
        __syncthreads();
    }
    m = red[0];
    __syncthreads();

    float sum = 0.0f;
    for (int i = tid; i < S_; i += 256) {
        float e = __expf(buf[i] - m);
        buf[i] = e;
        sum += e;
    }
    red[tid] = sum;
    __syncthreads();
#pragma unroll
    for (int s = 128; s > 0; s >>= 1) {
        if (tid < s) red[tid] += red[tid + s];
        __syncthreads();
    }
    const float inv = 1.0f / red[0];
    for (int i = tid; i < S_; i += 256) p[i] = buf[i] * inv;
}

extern "C" void kernel_launch(void* const* d_in, const int* in_sizes, int n_in,
                              void* d_out, int out_size)
{
    const float* query = (const float*)d_in[0];
    const float* key   = (const float*)d_in[1];
    const float* value = (const float*)d_in[2];
    const float* Wq    = (const float*)d_in[3];
    const float* bq    = (const float*)d_in[4];
    const float* Wk    = (const float*)d_in[5];
    const float* bk    = (const float*)d_in[6];
    const float* Wv    = (const float*)d_in[7];
    const float* bv    = (const float*)d_in[8];
    const float* Wo    = (const float*)d_in[9];
    const float* bo    = (const float*)d_in[10];

    float* out  = (float*)d_out;                        // [B,S,D]
    float* attn = out + (size_t)B_ * S_ * D_;           // [B,H,S,S]

    float *qb, *kb, *vb, *ob;
    cudaGetSymbolAddress((void**)&qb, g_q);
    cudaGetSymbolAddress((void**)&kb, g_k);
    cudaGetSymbolAddress((void**)&vb, g_v);
    cudaGetSymbolAddress((void**)&ob, g_o);

    const dim3 blk(256);
    const long long SD  = (long long)S_ * D_;
    const long long SS  = (long long)S_ * S_;
    const long long HSS = (long long)H_ * SS;

    // Q/K/V projections: [4096,1024] = [4096,1024] @ [1024,1024] + bias
    const dim3 gproj(D_ / 64, (B_ * S_) / 64, 1);
    gemm64<false, true><<<gproj, blk>>>(query, Wq, bq, qb,
        D_, D_, D_, D_, 1, 0, 0, 0, 0, 0, 0, 1.0f);
    gemm64<false, true><<<gproj, blk>>>(key, Wk, bk, kb,
        D_, D_, D_, D_, 1, 0, 0, 0, 0, 0, 0, 1.0f);
    gemm64<false, true><<<gproj, blk>>>(value, Wv, bv, vb,
        D_, D_, D_, D_, 1, 0, 0, 0, 0, 0, 0, 1.0f);

    // scores[bh] = (1/8) * Q_h @ K_h^T : 32 batches of [2048,2048,K=64]
    const dim3 gsc(S_ / 64, S_ / 64, B_ * H_);
    gemm64<true, false><<<gsc, blk>>>(qb, kb, nullptr, attn,
        HD_, D_, D_, S_, H_,
        SD, HD_, SD, HD_, HSS, SS, 0.125f);

    // softmax over last dim, in place in attn output buffer
    softmax_rows<<<B_ * H_ * S_, blk>>>(attn);

    // context[bh] = attn @ V_h : 32 batches of [2048,64,K=2048]
    const dim3 gpv(HD_ / 64, S_ / 64, B_ * H_);
    gemm64<false, false><<<gpv, blk>>>(attn, vb, nullptr, ob,
        S_, S_, D_, D_, H_,
        HSS, SS, SD, HD_, SD, HD_, 1.0f);

    // output projection: out = O @ Wo + bo
    gemm64<false, true><<<gproj, blk>>>(ob, Wo, bo, out,
        D_, D_, D_, D_, 1, 0, 0, 0, 0, 0, 0, 1.0f);
}

// round 2
// speedup vs baseline: 1.7788x; 1.7788x over previous
#include <cuda_runtime.h>

// Problem constants
#define B_ 2
#define S_ 2048
#define D_ 1024
#define H_ 16
#define HD_ 64

// Scratch (allocation-free contract)
__device__ float g_q[(size_t)B_ * S_ * D_];
__device__ float g_k[(size_t)B_ * S_ * D_];
__device__ float g_v[(size_t)B_ * S_ * D_];
__device__ float g_o[(size_t)B_ * S_ * D_];

// Tiled fp32 GEMM: C = scale * A @ B (+bias), batched via blockIdx.z.
// BM x BN block tile, BK k-slab, TM x TN per-thread micro-tile (TM=8, TN in {4,8}).
// TRANSB: B stored [N,K] row-major.
template <int BM, int BN, int BK, int TM, int TN, int THREADS,
          bool TRANSB, bool HASBIAS>
__global__ __launch_bounds__(THREADS) void gemm_tile(
    const float* __restrict__ Ag, const float* __restrict__ Bg,
    const float* __restrict__ bias, float* __restrict__ Cg,
    int K, int lda, int ldb, int ldc, int zdiv,
    long long sA1, long long sA2,
    long long sB1, long long sB2,
    long long sC1, long long sC2,
    float scale)
{
    static_assert(THREADS == (BM / TM) * (BN / TN), "thread count");
    constexpr int TX = BN / TN;        // threads along n
    constexpr int MH = TM / 4;         // 4-row groups per thread (1 or 2)
    constexpr int NH = TN / 4;         // 4-col groups per thread (1 or 2)

    __shared__ float As[BK][BM];       // k-major
    __shared__ float Bs[BK][BN];

    const int z  = blockIdx.z;
    const int zo = z / zdiv;
    const int zi = z - zo * zdiv;
    const float* A  = Ag + zo * sA1 + zi * sA2;
    const float* Bm = Bg + zo * sB1 + zi * sB2;
    float*       C  = Cg + zo * sC1 + zi * sC2;

    const int tid = threadIdx.x;
    const int tx  = tid % TX;
    const int ty  = tid / TX;
    const int row0 = blockIdx.y * BM;
    const int col0 = blockIdx.x * BN;

    float acc[TM][TN];
#pragma unroll
    for (int i = 0; i < TM; i++)
#pragma unroll
        for (int j = 0; j < TN; j++) acc[i][j] = 0.0f;

    for (int k0 = 0; k0 < K; k0 += BK) {
        // ---- load A tile (BM x BK) -> As[k][m], float4 along k, transpose-store
        constexpr int AV = (BM * BK) / (THREADS * 4);
#pragma unroll
        for (int l = 0; l < AV; l++) {
            int idx = tid + l * THREADS;
            int r  = idx / (BK / 4);
            int kp = (idx % (BK / 4)) * 4;
            float4 v = *reinterpret_cast<const float4*>(
                &A[(long long)(row0 + r) * lda + (k0 + kp)]);
            As[kp + 0][r] = v.x;
            As[kp + 1][r] = v.y;
            As[kp + 2][r] = v.z;
            As[kp + 3][r] = v.w;
        }
        // ---- load B tile -> Bs[k][n]
        if (TRANSB) {
            constexpr int BV = (BN * BK) / (THREADS * 4);
#pragma unroll
            for (int l = 0; l < BV; l++) {
                int idx = tid + l * THREADS;
                int n  = idx / (BK / 4);
                int kp = (idx % (BK / 4)) * 4;
                float4 v = *reinterpret_cast<const float4*>(
                    &Bm[(long long)(col0 + n) * ldb + (k0 + kp)]);
                Bs[kp + 0][n] = v.x;
                Bs[kp + 1][n] = v.y;
                Bs[kp + 2][n] = v.z;
                Bs[kp + 3][n] = v.w;
            }
        } else {
            constexpr int BV = (BN * BK) / (THREADS * 4);
#pragma unroll
            for (int l = 0; l < BV; l++) {
                int idx = tid + l * THREADS;
                int kk = idx / (BN / 4);
                int cp = (idx % (BN / 4)) * 4;
                *reinterpret_cast<float4*>(&Bs[kk][cp]) =
                    *reinterpret_cast<const float4*>(
                        &Bm[(long long)(k0 + kk) * ldb + (col0 + cp)]);
            }
        }
        __syncthreads();

#pragma unroll
        for (int kk = 0; kk < BK; kk++) {
            float a[TM], b[TN];
#pragma unroll
            for (int h = 0; h < MH; h++)
                *reinterpret_cast<float4*>(&a[h * 4]) =
                    *reinterpret_cast<const float4*>(&As[kk][h * (BM / MH) + ty * 4]);
#pragma unroll
            for (int h = 0; h < NH; h++)
                *reinterpret_cast<float4*>(&b[h * 4]) =
                    *reinterpret_cast<const float4*>(&Bs[kk][h * (BN / NH) + tx * 4]);
#pragma unroll
            for (int i = 0; i < TM; i++)
#pragma unroll
                for (int j = 0; j < TN; j++) acc[i][j] += a[i] * b[j];
        }
        __syncthreads();
    }

    // ---- epilogue: float4 stores
#pragma unroll
    for (int mh = 0; mh < MH; mh++) {
#pragma unroll
        for (int i = 0; i < 4; i++) {
            int m = row0 + mh * (BM / MH) + ty * 4 + i;
#pragma unroll
            for (int nh = 0; nh < NH; nh++) {
                int n = col0 + nh * (BN / NH) + tx * 4;
                float4 v;
                v.x = acc[mh * 4 + i][nh * 4 + 0] * scale;
                v.y = acc[mh * 4 + i][nh * 4 + 1] * scale;
                v.z = acc[mh * 4 + i][nh * 4 + 2] * scale;
                v.w = acc[mh * 4 + i][nh * 4 + 3] * scale;
                if (HASBIAS) {
                    v.x += bias[n + 0];
                    v.y += bias[n + 1];
                    v.z += bias[n + 2];
                    v.w += bias[n + 3];
                }
                *reinterpret_cast<float4*>(&C[(long long)m * ldc + n]) = v;
            }
        }
    }
}

// Row-wise softmax over S_=2048 elements, one block per row, in place. float4.
__global__ __launch_bounds__(256) void softmax_rows(float* __restrict__ attn)
{
    __shared__ float buf[S_];
    __shared__ float red[256];
    const long long row = blockIdx.x;
    float* p = attn + row * (long long)S_;
    const int tid = threadIdx.x;

    float m = -1e30f;
#pragma unroll
    for (int l = 0; l < 2; l++) {
        int i = (tid + l * 256) * 4;
        float4 x = *reinterpret_cast<const float4*>(&p[i]);
        *reinterpret_cast<float4*>(&buf[i]) = x;
        m = fmaxf(m, fmaxf(fmaxf(x.x, x.y), fmaxf(x.z, x.w)));
    }
    red[tid] = m;
    __syncthreads();
#pragma unroll
    for (int s = 128; s > 0; s >>= 1) {
        if (tid < s) red[tid] = fmaxf(red[tid], red[tid + s]);
        __syncthreads();
    }
    m = red[0];
    __syncthreads();

    float sum = 0.0f;
#pragma unroll
    for (int l = 0; l < 2; l++) {
        int i = (tid + l * 256) * 4;
        float4 x = *reinterpret_cast<float4*>(&buf[i]);
        x.x = __expf(x.x - m); x.y = __expf(x.y - m);
        x.z = __expf(x.z - m); x.w = __expf(x.w - m);
        *reinterpret_cast<float4*>(&buf[i]) = x;
        sum += x.x + x.y + x.z + x.w;
    }
    red[tid] = sum;
    __syncthreads();
#pragma unroll
    for (int s = 128; s > 0; s >>= 1) {
        if (tid < s) red[tid] += red[tid + s];
        __syncthreads();
    }
    const float inv = 1.0f / red[0];
#pragma unroll
    for (int l = 0; l < 2; l++) {
        int i = (tid + l * 256) * 4;
        float4 x = *reinterpret_cast<float4*>(&buf[i]);
        x.x *= inv; x.y *= inv; x.z *= inv; x.w *= inv;
        *reinterpret_cast<float4*>(&p[i]) = x;
    }
}

extern "C" void kernel_launch(void* const* d_in, const int* in_sizes, int n_in,
                              void* d_out, int out_size)
{
    const float* query = (const float*)d_in[0];
    const float* key   = (const float*)d_in[1];
    const float* value = (const float*)d_in[2];
    const float* Wq    = (const float*)d_in[3];
    const float* bq    = (const float*)d_in[4];
    const float* Wk    = (const float*)d_in[5];
    const float* bk    = (const float*)d_in[6];
    const float* Wv    = (const float*)d_in[7];
    const float* bv    = (const float*)d_in[8];
    const float* Wo    = (const float*)d_in[9];
    const float* bo    = (const float*)d_in[10];

    float* out  = (float*)d_out;                 // [B,S,D]
    float* attn = out + (size_t)B_ * S_ * D_;    // [B,H,S,S]

    float *qb, *kb, *vb, *ob;
    cudaGetSymbolAddress((void**)&qb, g_q);
    cudaGetSymbolAddress((void**)&kb, g_k);
    cudaGetSymbolAddress((void**)&vb, g_v);
    cudaGetSymbolAddress((void**)&ob, g_o);

    const long long SD  = (long long)S_ * D_;
    const long long SS  = (long long)S_ * S_;
    const long long HSS = (long long)H_ * SS;

    // Q/K/V projections: [4096,1024] @ [1024,1024] + bias
    const dim3 gproj(D_ / 128, (B_ * S_) / 128, 1);
    gemm_tile<128, 128, 8, 8, 8, 256, false, true><<<gproj, 256>>>(
        query, Wq, bq, qb, D_, D_, D_, D_, 1, 0, 0, 0, 0, 0, 0, 1.0f);
    gemm_tile<128, 128, 8, 8, 8, 256, false, true><<<gproj, 256>>>(
        key, Wk, bk, kb, D_, D_, D_, D_, 1, 0, 0, 0, 0, 0, 0, 1.0f);
    gemm_tile<128, 128, 8, 8, 8, 256, false, true><<<gproj, 256>>>(
        value, Wv, bv, vb, D_, D_, D_, D_, 1, 0, 0, 0, 0, 0, 0, 1.0f);

    // scores[bh] = (1/8) * Q_h @ K_h^T : 32 batches of [2048,2048,K=64]
    const dim3 gsc(S_ / 128, S_ / 128, B_ * H_);
    gemm_tile<128, 128, 8, 8, 8, 256, true, false><<<gsc, 256>>>(
        qb, kb, nullptr, attn, HD_, D_, D_, S_, H_,
        SD, HD_, SD, HD_, HSS, SS, 0.125f);

    // softmax over last dim, in place
    softmax_rows<<<B_ * H_ * S_, 256>>>(attn);

    // context[bh] = attn @ V_h : 32 batches of [2048,64,K=2048]
    const dim3 gpv(HD_ / 64, S_ / 128, B_ * H_);
    gemm_tile<128, 64, 16, 8, 8, 128, false, false><<<gpv, 128>>>(
        attn, vb, nullptr, ob, S_, S_, D_, D_, H_,
        HSS, SS, SD, HD_, SD, HD_, 1.0f);

    // output projection
    gemm_tile<128, 128, 8, 8, 8, 256, false, true><<<gproj, 256>>>(
        ob, Wo, bo, out, D_, D_, D_, D_, 1, 0, 0, 0, 0, 0, 0, 1.0f);
}

// round 4
// speedup vs baseline: 2.9512x; 1.6591x over previous
#include <cuda_runtime.h>
#include <cuda_bf16.h>
#include <cstdint>

#define B_ 2
#define S_ 2048
#define D_ 1024
#define H_ 16
#define HD_ 64

#define NELEM ((size_t)B_ * S_ * D_)

// ---------------- scratch (allocation-free contract) ----------------
__device__ __nv_bfloat16 g_qin_hi[NELEM], g_qin_lo[NELEM];
__device__ __nv_bfloat16 g_kin_hi[NELEM], g_kin_lo[NELEM];
__device__ __nv_bfloat16 g_vin_hi[NELEM], g_vin_lo[NELEM];
__device__ __nv_bfloat16 g_wt_hi[4 * D_ * D_], g_wt_lo[4 * D_ * D_]; // W^T [n][k]
__device__ __nv_bfloat16 g_q_hi[NELEM], g_q_lo[NELEM];
__device__ __nv_bfloat16 g_k_hi[NELEM], g_k_lo[NELEM];
__device__ float         g_v[NELEM];
__device__ __nv_bfloat16 g_vt_hi[NELEM], g_vt_lo[NELEM];  // [B*H, HD, S]
__device__ __nv_bfloat16 g_ctx_hi[NELEM], g_ctx_lo[NELEM];

// ---------------- baseline-PTX helpers (no sm_103a-only features) ----------------
__device__ __forceinline__ uint32_t smem_u32(const void* p) {
    uint32_t a;
    asm("{ .reg .u64 t; cvta.to.shared.u64 t, %1; cvt.u32.u64 %0, t; }" : "=r"(a) : "l"(p));
    return a;
}
#define CP_ASYNC16(dst, src) \
    asm volatile("cp.async.cg.shared.global [%0], [%1], 16;" :: "r"(dst), "l"(src))
#define CP_COMMIT() asm volatile("cp.async.commit_group;" ::: "memory")
#define CP_WAIT1()  asm volatile("cp.async.wait_group 1;" ::: "memory")
#define CP_WAIT0()  asm volatile("cp.async.wait_group 0;" ::: "memory")

#define LDMX4(r, a) \
    asm volatile("ldmatrix.sync.aligned.m8n8.x4.shared.b16 {%0,%1,%2,%3}, [%4];" \
        : "=r"((r)[0]), "=r"((r)[1]), "=r"((r)[2]), "=r"((r)[3]) : "r"(a))
#define LDMX2(r, a) \
    asm volatile("ldmatrix.sync.aligned.m8n8.x2.shared.b16 {%0,%1}, [%2];" \
        : "=r"((r)[0]), "=r"((r)[1]) : "r"(a))

#define MMA_BF16(d, a, b) \
    asm volatile("mma.sync.aligned.m16n8k16.row.col.f32.bf16.bf16.f32 " \
        "{%0,%1,%2,%3},{%4,%5,%6,%7},{%8,%9},{%0,%1,%2,%3};" \
        : "+f"((d)[0]), "+f"((d)[1]), "+f"((d)[2]), "+f"((d)[3]) \
        : "r"((a)[0]), "r"((a)[1]), "r"((a)[2]), "r"((a)[3]), "r"((b)[0]), "r"((b)[1]))

// ---------------- elementwise fp32 -> (hi,lo) bf16 split ----------------
__global__ __launch_bounds__(256) void split_kernel(
    const float* __restrict__ x, __nv_bfloat16* __restrict__ hi, __nv_bfloat16* __restrict__ lo)
{
    size_t base = ((size_t)blockIdx.x * 256 + threadIdx.x) * 4;
    float4 v = *reinterpret_cast<const float4*>(x + base);
    float f[4] = {v.x, v.y, v.z, v.w};
    alignas(8) __nv_bfloat16 h[4];
    alignas(8) __nv_bfloat16 l[4];
#pragma unroll
    for (int j = 0; j < 4; j++) {
        h[j] = __float2bfloat16(f[j]);
        l[j] = __float2bfloat16(f[j] - __bfloat162float(h[j]));
    }
    *reinterpret_cast<uint2*>(hi + base) = *reinterpret_cast<uint2*>(h);
    *reinterpret_cast<uint2*>(lo + base) = *reinterpret_cast<uint2*>(l);
}

// ---------------- weight transpose + split: W[k][n] -> Wt[n][k] ----------------
__global__ __launch_bounds__(256) void wtrans_kernel(
    const float* __restrict__ W, __nv_bfloat16* __restrict__ th, __nv_bfloat16* __restrict__ tl)
{
    __shared__ float t[32][33];
    const int tx = threadIdx.x, ty = threadIdx.y;
    const int n0 = blockIdx.x * 32, k0 = blockIdx.y * 32;
#pragma unroll
    for (int j = 0; j < 4; j++)
        t[ty + j * 8][tx] = W[(size_t)(k0 + ty + j * 8) * D_ + n0 + tx];
    __syncthreads();
#pragma unroll
    for (int j = 0; j < 4; j++) {
        float v = t[tx][ty + j * 8];
        __nv_bfloat16 h = __float2bfloat16(v);
        __nv_bfloat16 l = __float2bfloat16(v - __bfloat162float(h));
        size_t o = (size_t)(n0 + ty + j * 8) * D_ + k0 + tx;
        th[o] = h; tl[o] = l;
    }
}

// ---------------- V transpose + split: v[b,s,h*64+d] -> vt[(b*H+h)*64+d][s] ----------------
__global__ __launch_bounds__(256) void vtrans_kernel(
    const float* __restrict__ v, __nv_bfloat16* __restrict__ th, __nv_bfloat16* __restrict__ tl)
{
    __shared__ float t[32][33];
    const int tx = threadIdx.x, ty = threadIdx.y;
    const int s0 = blockIdx.x * 32, d0 = blockIdx.y * 32;
    const int z = blockIdx.z, b = z / H_, h = z % H_;
#pragma unroll
    for (int j = 0; j < 4; j++)
        t[ty + j * 8][tx] = v[(size_t)b * S_ * D_ + (size_t)(s0 + ty + j * 8) * D_ + h * HD_ + d0 + tx];
    __syncthreads();
#pragma unroll
    for (int j = 0; j < 4; j++) {
        float x = t[tx][ty + j * 8];
        __nv_bfloat16 hh = __float2bfloat16(x);
        __nv_bfloat16 ll = __float2bfloat16(x - __bfloat162float(hh));
        size_t o = ((size_t)z * HD_ + d0 + ty + j * 8) * S_ + s0 + tx;
        th[o] = hh; tl[o] = ll;
    }
}

// ---------------- warp-MMA GEMM (bf16 split, 3-MMA compensation) ----------------
// C[m,n] = scale * (sum_k A[m,k]*B[n,k] (+ bias[n]))
// A, B K-major. BM=128, BK=32 bf16 per slab, double-buffered cp.async pipeline.
// 8 warps as 2(M) x 4(N); warp tile 64 x (BN/4); HMMA m16n8k16.
template <int BN, bool AFP32, bool SPLITOUT, bool HASBIAS>
__global__ __launch_bounds__(256, 1) void gemm_mma(
    const __nv_bfloat16* __restrict__ AhG, const __nv_bfloat16* __restrict__ AlG,
    const float* __restrict__ AfG,
    const __nv_bfloat16* __restrict__ BhG, const __nv_bfloat16* __restrict__ BlG,
    const float* __restrict__ bias,
    float* __restrict__ CfG, __nv_bfloat16* __restrict__ ChG, __nv_bfloat16* __restrict__ ClG,
    int K, int lda, int ldb, int ldc, int zdiv,
    long long sA1, long long sA2, long long sB1, long long sB2,
    long long sC1, long long sC2, float scale)
{
    extern __shared__ char smem[];
    constexpr int AN = BN / 32;                 // n-fragments per warp
    constexpr uint32_t A_BUF = 128 * 80;        // 10240 B, padded rows of 80 B
    constexpr uint32_t B_BUF = BN * 80;
    const uint32_t sbase = smem_u32(smem);

    const int tid = threadIdx.x;
    const int wid = tid >> 5, lane = tid & 31;
    const int wm0 = (wid >> 2) * 64;
    const int wn0 = (wid & 3) * (BN / 4);

    const int z  = blockIdx.z;
    const int zo = z / zdiv, zi = z - zo * zdiv;
    const long long aoff = zo * sA1 + zi * sA2;
    const long long boff = zo * sB1 + zi * sB2;
    const long long coff = zo * sC1 + zi * sC2;
    const int row0 = blockIdx.y * 128, col0 = blockIdx.x * BN;

    const __nv_bfloat16* Ah_p = AFP32 ? nullptr : (AhG + aoff);
    const __nv_bfloat16* Al_p = AFP32 ? nullptr : (AlG + aoff);
    const float*         Af_p = AFP32 ? (AfG + aoff) : nullptr;
    const __nv_bfloat16* Bh_p = BhG + boff;
    const __nv_bfloat16* Bl_p = BlG + boff;

    float acc[4][AN][4];
#pragma unroll
    for (int im = 0; im < 4; im++)
#pragma unroll
        for (int in_ = 0; in_ < AN; in_++)
#pragma unroll
            for (int j = 0; j < 4; j++) acc[im][in_][j] = 0.0f;

    auto produce = [&](int i) {
        const int b = i & 1;
        const int k0 = i << 5;
        if (AFP32) {
#pragma unroll
            for (int c = tid; c < 512; c += 256) {
                int r = c >> 2, kc = c & 3;
                const float* s = Af_p + (long long)(row0 + r) * lda + k0 + kc * 8;
                float4 u0 = *reinterpret_cast<const float4*>(s);
                float4 u1 = *reinterpret_cast<const float4*>(s + 4);
                float f[8] = {u0.x, u0.y, u0.z, u0.w, u1.x, u1.y, u1.z, u1.w};
                alignas(16) __nv_bfloat16 hh[8];
                alignas(16) __nv_bfloat16 ll[8];
#pragma unroll
                for (int j = 0; j < 8; j++) {
                    hh[j] = __float2bfloat16(f[j]);
                    ll[j] = __float2bfloat16(f[j] - __bfloat162float(hh[j]));
                }
                uint32_t off = (uint32_t)(r * 80 + kc * 16);
                *reinterpret_cast<uint4*>(smem + b * A_BUF + off) = *reinterpret_cast<uint4*>(hh);
                *reinterpret_cast<uint4*>(smem + 2 * A_BUF + b * A_BUF + off) = *reinterpret_cast<uint4*>(ll);
            }
        } else {
#pragma unroll
            for (int c = tid; c < 512; c += 256) {
                int r = c >> 2, kc = c & 3;
                long long o = (long long)(row0 + r) * lda + k0 + kc * 8;
                uint32_t d = sbase + (uint32_t)(r * 80 + kc * 16);
                CP_ASYNC16(d + b * A_BUF, Ah_p + o);
                CP_ASYNC16(d + 2 * A_BUF + b * A_BUF, Al_p + o);
            }
        }
#pragma unroll
        for (int c = tid; c < BN * 4; c += 256) {
            int r = c >> 2, kc = c & 3;
            long long o = (long long)(col0 + r) * ldb + k0 + kc * 8;
            uint32_t d = sbase + 4 * A_BUF + (uint32_t)(r * 80 + kc * 16);
            CP_ASYNC16(d + b * B_BUF, Bh_p + o);
            CP_ASYNC16(d + 2 * B_BUF + b * B_BUF, Bl_p + o);
        }
        CP_COMMIT();
    };

    auto compute = [&](int b) {
        const uint32_t bAh = sbase + b * A_BUF;
        const uint32_t bAl = bAh + 2 * A_BUF;
        const uint32_t bBh = sbase + 4 * A_BUF + b * B_BUF;
        const uint32_t bBl = bBh + 2 * B_BUF;
#pragma unroll
        for (int k2 = 0; k2 < 2; k2++) {
            uint32_t ah[4][4], al[4][4];
            const uint32_t ao = (uint32_t)((wm0 + (lane & 15)) * 80 +
                                           (k2 * 16 + (lane >> 4) * 8) * 2);
#pragma unroll
            for (int im = 0; im < 4; im++) {
                LDMX4(ah[im], bAh + ao + im * (16 * 80));
                LDMX4(al[im], bAl + ao + im * (16 * 80));
            }
            const uint32_t bo = (uint32_t)((wn0 + (lane & 7)) * 80 +
                                           (k2 * 16 + ((lane >> 3) & 1) * 8) * 2);
#pragma unroll
            for (int in_ = 0; in_ < AN; in_++) {
                uint32_t bh[2], bl[2];
                LDMX2(bh, bBh + bo + in_ * (8 * 80));
                LDMX2(bl, bBl + bo + in_ * (8 * 80));
#pragma unroll
                for (int im = 0; im < 4; im++) {
                    MMA_BF16(acc[im][in_], ah[im], bh);
                    MMA_BF16(acc[im][in_], ah[im], bl);
                    MMA_BF16(acc[im][in_], al[im], bh);
                }
            }
        }
    };

    const int NS = K >> 5;
    produce(0);
    produce(1);
    for (int i = 0; i < NS; i++) {
        if (i + 1 < NS) { CP_WAIT1(); } else { CP_WAIT0(); }
        __syncthreads();
        compute(i & 1);
        __syncthreads();
        if (i + 2 < NS) produce(i + 2);
    }

    // ---- epilogue
    const int qrow = lane >> 2;
    const int qcol = (lane & 3) * 2;
#pragma unroll
    for (int im = 0; im < 4; im++) {
#pragma unroll
        for (int half = 0; half < 2; half++) {
            const int m = row0 + wm0 + im * 16 + qrow + half * 8;
#pragma unroll
            for (int in_ = 0; in_ < AN; in_++) {
                const int n = col0 + wn0 + in_ * 8 + qcol;
                float v0 = acc[im][in_][half * 2 + 0];
                float v1 = acc[im][in_][half * 2 + 1];
                if (HASBIAS) { v0 += bias[n]; v1 += bias[n + 1]; }
                v0 *= scale; v1 *= scale;
                const long long o = coff + (long long)m * ldc + n;
                if (SPLITOUT) {
                    __nv_bfloat16 h0 = __float2bfloat16(v0);
                    __nv_bfloat16 h1 = __float2bfloat16(v1);
                    __nv_bfloat16 l0 = __float2bfloat16(v0 - __bfloat162float(h0));
                    __nv_bfloat16 l1 = __float2bfloat16(v1 - __bfloat162float(h1));
                    uint32_t hp = ((uint32_t)__bfloat16_as_ushort(h1) << 16) |
                                  (uint32_t)__bfloat16_as_ushort(h0);
                    uint32_t lp = ((uint32_t)__bfloat16_as_ushort(l1) << 16) |
                                  (uint32_t)__bfloat16_as_ushort(l0);
                    *reinterpret_cast<uint32_t*>(ChG + o) = hp;
                    *reinterpret_cast<uint32_t*>(ClG + o) = lp;
                } else {
                    float2 w = make_float2(v0, v1);
                    *reinterpret_cast<float2*>(CfG + o) = w;
                }
            }
        }
    }
}

// ---------------- softmax ----------------
__global__ __launch_bounds__(256) void softmax_rows(float* __restrict__ attn)
{
    __shared__ float buf[S_];
    __shared__ float red[256];
    const long long row = blockIdx.x;
    float* p = attn + row * (long long)S_;
    const int tid = threadIdx.x;

    float m = -1e30f;
#pragma unroll
    for (int l = 0; l < 2; l++) {
        int i = (tid + l * 256) * 4;
        float4 x = *reinterpret_cast<const float4*>(&p[i]);
        *reinterpret_cast<float4*>(&buf[i]) = x;
        m = fmaxf(m, fmaxf(fmaxf(x.x, x.y), fmaxf(x.z, x.w)));
    }
    red[tid] = m;
    __syncthreads();
#pragma unroll
    for (int s = 128; s > 0; s >>= 1) {
        if (tid < s) red[tid] = fmaxf(red[tid], red[tid + s]);
        __syncthreads();
    }
    m = red[0];
    __syncthreads();

    float sum = 0.0f;
#pragma unroll
    for (int l = 0; l < 2; l++) {
        int i = (tid + l * 256) * 4;
        float4 x = *reinterpret_cast<float4*>(&buf[i]);
        x.x = __expf(x.x - m); x.y = __expf(x.y - m);
        x.z = __expf(x.z - m); x.w = __expf(x.w - m);
        *reinterpret_cast<float4*>(&buf[i]) = x;
        sum += x.x + x.y + x.z + x.w;
    }
    red[tid] = sum;
    __syncthreads();
#pragma unroll
    for (int s = 128; s > 0; s >>= 1) {
        if (tid < s) red[tid] += red[tid + s];
        __syncthreads();
    }
    const float inv = 1.0f / red[0];
#pragma unroll
    for (int l = 0; l < 2; l++) {
        int i = (tid + l * 256) * 4;
        float4 x = *reinterpret_cast<float4*>(&buf[i]);
        x.x *= inv; x.y *= inv; x.z *= inv; x.w *= inv;
        *reinterpret_cast<float4*>(&p[i]) = x;
    }
}

// ---------------- host ----------------
extern "C" void kernel_launch(void* const* d_in, const int* in_sizes, int n_in,
                              void* d_out, int out_size)
{
    const float* query = (const float*)d_in[0];
    const float* key   = (const float*)d_in[1];
    const float* value = (const float*)d_in[2];
    const float* Wq = (const float*)d_in[3];
    const float* bq = (const float*)d_in[4];
    const float* Wk = (const float*)d_in[5];
    const float* bk = (const float*)d_in[6];
    const float* Wv = (const float*)d_in[7];
    const float* bv = (const float*)d_in[8];
    const float* Wo = (const float*)d_in[9];
    const float* bo = (const float*)d_in[10];

    float* out  = (float*)d_out;
    float* attn = out + NELEM;

    __nv_bfloat16 *qin_hi, *qin_lo, *kin_hi, *kin_lo, *vin_hi, *vin_lo;
    __nv_bfloat16 *wt_hi, *wt_lo, *q_hi, *q_lo, *k_hi, *k_lo;
    __nv_bfloat16 *vt_hi, *vt_lo, *ctx_hi, *ctx_lo;
    float* vbuf;
    cudaGetSymbolAddress((void**)&qin_hi, g_qin_hi);
    cudaGetSymbolAddress((void**)&qin_lo, g_qin_lo);
    cudaGetSymbolAddress((void**)&kin_hi, g_kin_hi);
    cudaGetSymbolAddress((void**)&kin_lo, g_kin_lo);
    cudaGetSymbolAddress((void**)&vin_hi, g_vin_hi);
    cudaGetSymbolAddress((void**)&vin_lo, g_vin_lo);
    cudaGetSymbolAddress((void**)&wt_hi, g_wt_hi);
    cudaGetSymbolAddress((void**)&wt_lo, g_wt_lo);
    cudaGetSymbolAddress((void**)&q_hi, g_q_hi);
    cudaGetSymbolAddress((void**)&q_lo, g_q_lo);
    cudaGetSymbolAddress((void**)&k_hi, g_k_hi);
    cudaGetSymbolAddress((void**)&k_lo, g_k_lo);
    cudaGetSymbolAddress((void**)&vbuf, g_v);
    cudaGetSymbolAddress((void**)&vt_hi, g_vt_hi);
    cudaGetSymbolAddress((void**)&vt_lo, g_vt_lo);
    cudaGetSymbolAddress((void**)&ctx_hi, g_ctx_hi);
    cudaGetSymbolAddress((void**)&ctx_lo, g_ctx_lo);

    auto GP_split = gemm_mma<128, false, true,  true >;  // Q,K projections
    auto GP_f32b  = gemm_mma<128, false, false, true >;  // V, out projections
    auto GS       = gemm_mma<128, false, false, false>;  // scores
    auto GPV      = gemm_mma<64,  true,  true,  false>;  // PV
    const int SM128 = 4 * 128 * 80 + 4 * 128 * 80;       // 81920
    const int SM64  = 4 * 128 * 80 + 4 * 64 * 80;        // 61440
    cudaFuncSetAttribute(GP_split, cudaFuncAttributeMaxDynamicSharedMemorySize, SM128);
    cudaFuncSetAttribute(GP_f32b,  cudaFuncAttributeMaxDynamicSharedMemorySize, SM128);
    cudaFuncSetAttribute(GS,       cudaFuncAttributeMaxDynamicSharedMemorySize, SM128);
    cudaFuncSetAttribute(GPV,      cudaFuncAttributeMaxDynamicSharedMemorySize, SM64);

    const long long SD  = (long long)S_ * D_;
    const long long SS  = (long long)S_ * S_;
    const long long HSS = (long long)H_ * SS;

    // 1) split inputs to bf16 hi/lo
    const int nsplit = (int)(NELEM / 1024);
    split_kernel<<<nsplit, 256>>>(query, qin_hi, qin_lo);
    split_kernel<<<nsplit, 256>>>(key,   kin_hi, kin_lo);
    split_kernel<<<nsplit, 256>>>(value, vin_hi, vin_lo);

    // 2) transpose + split weights
    const dim3 wtb(32, 8), wtg(32, 32);
    wtrans_kernel<<<wtg, wtb>>>(Wq, wt_hi + 0 * D_ * D_, wt_lo + 0 * D_ * D_);
    wtrans_kernel<<<wtg, wtb>>>(Wk, wt_hi + 1 * D_ * D_, wt_lo + 1 * D_ * D_);
    wtrans_kernel<<<wtg, wtb>>>(Wv, wt_hi + 2 * D_ * D_, wt_lo + 2 * D_ * D_);
    wtrans_kernel<<<wtg, wtb>>>(Wo, wt_hi + 3 * D_ * D_, wt_lo + 3 * D_ * D_);

    // 3) projections (Q folds the 1/sqrt(HD)=0.125 scale, applied after bias)
    const dim3 gproj(D_ / 128, (B_ * S_) / 128, 1);
    GP_split<<<gproj, 256, SM128>>>(qin_hi, qin_lo, nullptr, wt_hi + 0 * D_ * D_, wt_lo + 0 * D_ * D_,
        bq, nullptr, q_hi, q_lo, D_, D_, D_, D_, 1, 0, 0, 0, 0, 0, 0, 0.125f);
    GP_split<<<gproj, 256, SM128>>>(kin_hi, kin_lo, nullptr, wt_hi + 1 * D_ * D_, wt_lo + 1 * D_ * D_,
        bk, nullptr, k_hi, k_lo, D_, D_, D_, D_, 1, 0, 0, 0, 0, 0, 0, 1.0f);
    GP_f32b<<<gproj, 256, SM128>>>(vin_hi, vin_lo, nullptr, wt_hi + 2 * D_ * D_, wt_lo + 2 * D_ * D_,
        bv, vbuf, nullptr, nullptr, D_, D_, D_, D_, 1, 0, 0, 0, 0, 0, 0, 1.0f);

    // 4) transpose + split V -> vt [B*H, HD, S]
    vtrans_kernel<<<dim3(S_ / 32, HD_ / 32, B_ * H_), wtb>>>(vbuf, vt_hi, vt_lo);

    // 5) scores = q_scaled @ k^T -> attn fp32
    GS<<<dim3(S_ / 128, S_ / 128, B_ * H_), 256, SM128>>>(
        q_hi, q_lo, nullptr, k_hi, k_lo, nullptr, attn, nullptr, nullptr,
        HD_, D_, D_, S_, H_, SD, HD_, SD, HD_, HSS, SS, 1.0f);

    // 6) softmax in place
    softmax_rows<<<B_ * H_ * S_, 256>>>(attn);

    // 7) ctx = attn @ V  (attn fp32 converted in-kernel; vt pre-split)
    GPV<<<dim3(1, S_ / 128, B_ * H_), 256, SM64>>>(
        nullptr, nullptr, attn, vt_hi, vt_lo, nullptr, nullptr, ctx_hi, ctx_lo,
        S_, S_, S_, D_, H_, HSS, SS, (long long)H_ * HD_ * S_, (long long)HD_ * S_, SD, HD_, 1.0f);

    // 8) out = ctx @ Wo + bo
    GP_f32b<<<gproj, 256, SM128>>>(ctx_hi, ctx_lo, nullptr, wt_hi + 3 * D_ * D_, wt_lo + 3 * D_ * D_,
        bo, out, nullptr, nullptr, D_, D_, D_, D_, 1, 0, 0, 0, 0, 0, 0, 1.0f);
}

// round 5
// speedup vs baseline: 3.6124x; 1.2240x over previous
#include <cuda_runtime.h>
#include <cuda_fp16.h>
#include <cstdint>

#define B_ 2
#define S_ 2048
#define D_ 1024
#define H_ 16
#define HD_ 64

#define NELEM ((size_t)B_ * S_ * D_)

// ---------------- scratch (allocation-free contract) ----------------
__device__ __half g_qin[NELEM], g_kin[NELEM], g_vin[NELEM];
__device__ __half g_wt_hi[4 * D_ * D_], g_wt_lo[4 * D_ * D_];  // W^T [n][k] fp16 hi/lo
__device__ __half g_q16[NELEM], g_k16[NELEM];
__device__ float  g_v[NELEM];
__device__ __half g_vt[NELEM];      // [B*H, HD, S]
__device__ __half g_ctx[NELEM];

// ---------------- baseline-PTX helpers ----------------
__device__ __forceinline__ uint32_t smem_u32(const void* p) {
    uint32_t a;
    asm("{ .reg .u64 t; cvta.to.shared.u64 t, %1; cvt.u32.u64 %0, t; }" : "=r"(a) : "l"(p));
    return a;
}
#define CP_ASYNC16(dst, src) \
    asm volatile("cp.async.cg.shared.global [%0], [%1], 16;" :: "r"(dst), "l"(src))
#define CP_COMMIT() asm volatile("cp.async.commit_group;" ::: "memory")
#define CP_WAIT1()  asm volatile("cp.async.wait_group 1;" ::: "memory")
#define CP_WAIT0()  asm volatile("cp.async.wait_group 0;" ::: "memory")

#define LDMX4(r, a) \
    asm volatile("ldmatrix.sync.aligned.m8n8.x4.shared.b16 {%0,%1,%2,%3}, [%4];" \
        : "=r"((r)[0]), "=r"((r)[1]), "=r"((r)[2]), "=r"((r)[3]) : "r"(a))
#define LDMX2(r, a) \
    asm volatile("ldmatrix.sync.aligned.m8n8.x2.shared.b16 {%0,%1}, [%2];" \
        : "=r"((r)[0]), "=r"((r)[1]) : "r"(a))

#define MMA_F16(d, a, b) \
    asm volatile("mma.sync.aligned.m16n8k16.row.col.f32.f16.f16.f32 " \
        "{%0,%1,%2,%3},{%4,%5,%6,%7},{%8,%9},{%0,%1,%2,%3};" \
        : "+f"((d)[0]), "+f"((d)[1]), "+f"((d)[2]), "+f"((d)[3]) \
        : "r"((a)[0]), "r"((a)[1]), "r"((a)[2]), "r"((a)[3]), "r"((b)[0]), "r"((b)[1]))

// ---------------- fp32 -> fp16 cast ----------------
__global__ __launch_bounds__(256) void cast_kernel(
    const float* __restrict__ x, __half* __restrict__ y)
{
    size_t base = ((size_t)blockIdx.x * 256 + threadIdx.x) * 4;
    float4 v = *reinterpret_cast<const float4*>(x + base);
    alignas(8) __half h[4];
    h[0] = __float2half_rn(v.x); h[1] = __float2half_rn(v.y);
    h[2] = __float2half_rn(v.z); h[3] = __float2half_rn(v.w);
    *reinterpret_cast<uint2*>(y + base) = *reinterpret_cast<uint2*>(h);
}

// ---------------- weight transpose + fp16 hi/lo split: W[k][n] -> Wt[n][k] ----------------
__global__ __launch_bounds__(256) void wtrans_kernel(
    const float* __restrict__ W, __half* __restrict__ th, __half* __restrict__ tl)
{
    __shared__ float t[32][33];
    const int tx = threadIdx.x, ty = threadIdx.y;
    const int n0 = blockIdx.x * 32, k0 = blockIdx.y * 32;
#pragma unroll
    for (int j = 0; j < 4; j++)
        t[ty + j * 8][tx] = W[(size_t)(k0 + ty + j * 8) * D_ + n0 + tx];
    __syncthreads();
#pragma unroll
    for (int j = 0; j < 4; j++) {
        float v = t[tx][ty + j * 8];
        __half h = __float2half_rn(v);
        __half l = __float2half_rn(v - __half2float(h));
        size_t o = (size_t)(n0 + ty + j * 8) * D_ + k0 + tx;
        th[o] = h; tl[o] = l;
    }
}

// ---------------- V transpose -> fp16: v[b,s,h*64+d] -> vt[(b*H+h)*64+d][s] ----------------
__global__ __launch_bounds__(256) void vtrans_kernel(
    const float* __restrict__ v, __half* __restrict__ th)
{
    __shared__ float t[32][33];
    const int tx = threadIdx.x, ty = threadIdx.y;
    const int s0 = blockIdx.x * 32, d0 = blockIdx.y * 32;
    const int z = blockIdx.z, b = z / H_, h = z % H_;
#pragma unroll
    for (int j = 0; j < 4; j++)
        t[ty + j * 8][tx] = v[(size_t)b * S_ * D_ + (size_t)(s0 + ty + j * 8) * D_ + h * HD_ + d0 + tx];
    __syncthreads();
#pragma unroll
    for (int j = 0; j < 4; j++) {
        size_t o = ((size_t)z * HD_ + d0 + ty + j * 8) * S_ + s0 + tx;
        th[o] = __float2half_rn(t[tx][ty + j * 8]);
    }
}

// ---------------- warp-MMA GEMM (fp16, selective compensation) ----------------
// C[m,n] = scale * (sum_k A[m,k]*B[n,k] (+ bias[n]))
// ASPLIT: A is fp32 in gmem, converted to (hi,lo) fp16 in-kernel, 2-MMA A-compensation.
// BSPLIT: B has precomputed fp16 hi/lo arrays, 2-MMA B-compensation.
// 8 warps as 2(M) x 4(N); warp tile 64 x (BN/4); BM=128, BK=32 slabs double-buffered.
template <int BN, bool ASPLIT, bool BSPLIT, bool OUT16, bool HASBIAS>
__global__ __launch_bounds__(256, 1) void gemm_mma(
    const __half* __restrict__ A16, const float* __restrict__ Af,
    const __half* __restrict__ BhG, const __half* __restrict__ BlG,
    const float* __restrict__ bias,
    float* __restrict__ CfG, __half* __restrict__ C16G,
    int K, int lda, int ldb, int ldc, int zdiv,
    long long sA1, long long sA2, long long sB1, long long sB2,
    long long sC1, long long sC2, float scale)
{
    extern __shared__ char smem[];
    constexpr int AN = BN / 32;                 // n-fragments per warp
    constexpr int ACOMP = ASPLIT ? 2 : 1;
    constexpr int BCOMP = BSPLIT ? 2 : 1;
    constexpr uint32_t A_STAGE = 128 * 80;      // 80B padded rows (64B data)
    constexpr uint32_t B_STAGE = BN * 80;
    constexpr uint32_t B_BASE = 2 * ACOMP * A_STAGE;
    const uint32_t sbase = smem_u32(smem);

    const int tid = threadIdx.x;
    const int wid = tid >> 5, lane = tid & 31;
    const int wm0 = (wid >> 2) * 64;
    const int wn0 = (wid & 3) * (BN / 4);

    const int z  = blockIdx.z;
    const int zo = z / zdiv, zi = z - zo * zdiv;
    const long long aoff = zo * sA1 + zi * sA2;
    const long long boff = zo * sB1 + zi * sB2;
    const long long coff = zo * sC1 + zi * sC2;
    const int row0 = blockIdx.y * 128, col0 = blockIdx.x * BN;

    const __half* A16_p = ASPLIT ? nullptr : (A16 + aoff);
    const float*  Af_p  = ASPLIT ? (Af + aoff) : nullptr;
    const __half* Bh_p  = BhG + boff;
    const __half* Bl_p  = BSPLIT ? (BlG + boff) : nullptr;

    float acc[4][AN][4];
#pragma unroll
    for (int im = 0; im < 4; im++)
#pragma unroll
        for (int in_ = 0; in_ < AN; in_++)
#pragma unroll
            for (int j = 0; j < 4; j++) acc[im][in_][j] = 0.0f;

    auto produce = [&](int i) {
        const int st = i & 1;
        const int k0 = i << 5;
        if (ASPLIT) {
#pragma unroll
            for (int c = tid; c < 512; c += 256) {
                int r = c >> 2, kc = c & 3;
                const float* s = Af_p + (long long)(row0 + r) * lda + k0 + kc * 8;
                float4 u0 = *reinterpret_cast<const float4*>(s);
                float4 u1 = *reinterpret_cast<const float4*>(s + 4);
                float f[8] = {u0.x, u0.y, u0.z, u0.w, u1.x, u1.y, u1.z, u1.w};
                alignas(16) __half hh[8];
                alignas(16) __half ll[8];
#pragma unroll
                for (int j = 0; j < 8; j++) {
                    hh[j] = __float2half_rn(f[j]);
                    ll[j] = __float2half_rn(f[j] - __half2float(hh[j]));
                }
                uint32_t off = (uint32_t)(r * 80 + kc * 16);
                *reinterpret_cast<uint4*>(smem + (st * 2 + 0) * A_STAGE + off) = *reinterpret_cast<uint4*>(hh);
                *reinterpret_cast<uint4*>(smem + (st * 2 + 1) * A_STAGE + off) = *reinterpret_cast<uint4*>(ll);
            }
        } else {
#pragma unroll
            for (int c = tid; c < 512; c += 256) {
                int r = c >> 2, kc = c & 3;
                long long o = (long long)(row0 + r) * lda + k0 + kc * 8;
                CP_ASYNC16(sbase + st * A_STAGE + (uint32_t)(r * 80 + kc * 16), A16_p + o);
            }
        }
#pragma unroll
        for (int c = tid; c < BN * 4; c += 256) {
            int r = c >> 2, kc = c & 3;
            long long o = (long long)(col0 + r) * ldb + k0 + kc * 8;
            uint32_t d = sbase + B_BASE + (uint32_t)(r * 80 + kc * 16);
            CP_ASYNC16(d + st * BCOMP * B_STAGE, Bh_p + o);
            if (BSPLIT)
                CP_ASYNC16(d + (st * BCOMP + 1) * B_STAGE, Bl_p + o);
        }
        CP_COMMIT();
    };

    auto compute = [&](int st) {
        const uint32_t bAh = sbase + st * ACOMP * A_STAGE;
        const uint32_t bAl = bAh + A_STAGE;
        const uint32_t bBh = sbase + B_BASE + st * BCOMP * B_STAGE;
        const uint32_t bBl = bBh + B_STAGE;
#pragma unroll
        for (int k2 = 0; k2 < 2; k2++) {
            uint32_t ah[4][4], al[4][4];
            const uint32_t ao = (uint32_t)((wm0 + (lane & 15)) * 80 +
                                           (k2 * 16 + (lane >> 4) * 8) * 2);
#pragma unroll
            for (int im = 0; im < 4; im++) {
                LDMX4(ah[im], bAh + ao + im * (16 * 80));
                if (ASPLIT) LDMX4(al[im], bAl + ao + im * (16 * 80));
            }
            const uint32_t bo = (uint32_t)((wn0 + (lane & 7)) * 80 +
                                           (k2 * 16 + ((lane >> 3) & 1) * 8) * 2);
#pragma unroll
            for (int in_ = 0; in_ < AN; in_++) {
                uint32_t bh[2], bl[2];
                LDMX2(bh, bBh + bo + in_ * (8 * 80));
                if (BSPLIT) LDMX2(bl, bBl + bo + in_ * (8 * 80));
#pragma unroll
                for (int im = 0; im < 4; im++) {
                    MMA_F16(acc[im][in_], ah[im], bh);
                    if (BSPLIT) MMA_F16(acc[im][in_], ah[im], bl);
                    if (ASPLIT) MMA_F16(acc[im][in_], al[im], bh);
                }
            }
        }
    };

    const int NS = K >> 5;
    produce(0);
    produce(1);
    for (int i = 0; i < NS; i++) {
        if (i + 1 < NS) { CP_WAIT1(); } else { CP_WAIT0(); }
        __syncthreads();
        compute(i & 1);
        __syncthreads();
        if (i + 2 < NS) produce(i + 2);
    }

    // ---- epilogue
    const int qrow = lane >> 2;
    const int qcol = (lane & 3) * 2;
#pragma unroll
    for (int im = 0; im < 4; im++) {
#pragma unroll
        for (int half_ = 0; half_ < 2; half_++) {
            const int m = row0 + wm0 + im * 16 + qrow + half_ * 8;
#pragma unroll
            for (int in_ = 0; in_ < AN; in_++) {
                const int n = col0 + wn0 + in_ * 8 + qcol;
                float v0 = acc[im][in_][half_ * 2 + 0];
                float v1 = acc[im][in_][half_ * 2 + 1];
                if (HASBIAS) { v0 += bias[n]; v1 += bias[n + 1]; }
                v0 *= scale; v1 *= scale;
                const long long o = coff + (long long)m * ldc + n;
                if (OUT16) {
                    __half h0 = __float2half_rn(v0);
                    __half h1 = __float2half_rn(v1);
                    uint32_t hp = ((uint32_t)__half_as_ushort(h1) << 16) |
                                  (uint32_t)__half_as_ushort(h0);
                    *reinterpret_cast<uint32_t*>(C16G + o) = hp;
                } else {
                    float2 w = make_float2(v0, v1);
                    *reinterpret_cast<float2*>(CfG + o) = w;
                }
            }
        }
    }
}

// ---------------- softmax ----------------
__global__ __launch_bounds__(256) void softmax_rows(float* __restrict__ attn)
{
    __shared__ float buf[S_];
    __shared__ float red[256];
    const long long row = blockIdx.x;
    float* p = attn + row * (long long)S_;
    const int tid = threadIdx.x;

    float m = -1e30f;
#pragma unroll
    for (int l = 0; l < 2; l++) {
        int i = (tid + l * 256) * 4;
        float4 x = *reinterpret_cast<const float4*>(&p[i]);
        *reinterpret_cast<float4*>(&buf[i]) = x;
        m = fmaxf(m, fmaxf(fmaxf(x.x, x.y), fmaxf(x.z, x.w)));
    }
    red[tid] = m;
    __syncthreads();
#pragma unroll
    for (int s = 128; s > 0; s >>= 1) {
        if (tid < s) red[tid] = fmaxf(red[tid], red[tid + s]);
        __syncthreads();
    }
    m = red[0];
    __syncthreads();

    float sum = 0.0f;
#pragma unroll
    for (int l = 0; l < 2; l++) {
        int i = (tid + l * 256) * 4;
        float4 x = *reinterpret_cast<float4*>(&buf[i]);
        x.x = __expf(x.x - m); x.y = __expf(x.y - m);
        x.z = __expf(x.z - m); x.w = __expf(x.w - m);
        *reinterpret_cast<float4*>(&buf[i]) = x;
        sum += x.x + x.y + x.z + x.w;
    }
    red[tid] = sum;
    __syncthreads();
#pragma unroll
    for (int s = 128; s > 0; s >>= 1) {
        if (tid < s) red[tid] += red[tid + s];
        __syncthreads();
    }
    const float inv = 1.0f / red[0];
#pragma unroll
    for (int l = 0; l < 2; l++) {
        int i = (tid + l * 256) * 4;
        float4 x = *reinterpret_cast<float4*>(&buf[i]);
        x.x *= inv; x.y *= inv; x.z *= inv; x.w *= inv;
        *reinterpret_cast<float4*>(&p[i]) = x;
    }
}

// ---------------- host ----------------
extern "C" void kernel_launch(void* const* d_in, const int* in_sizes, int n_in,
                              void* d_out, int out_size)
{
    const float* query = (const float*)d_in[0];
    const float* key   = (const float*)d_in[1];
    const float* value = (const float*)d_in[2];
    const float* Wq = (const float*)d_in[3];
    const float* bq = (const float*)d_in[4];
    const float* Wk = (const float*)d_in[5];
    const float* bk = (const float*)d_in[6];
    const float* Wv = (const float*)d_in[7];
    const float* bv = (const float*)d_in[8];
    const float* Wo = (const float*)d_in[9];
    const float* bo = (const float*)d_in[10];

    float* out  = (float*)d_out;
    float* attn = out + NELEM;

    __half *qin, *kin, *vin, *wt_hi, *wt_lo, *q16, *k16, *vt, *ctx;
    float* vbuf;
    cudaGetSymbolAddress((void**)&qin, g_qin);
    cudaGetSymbolAddress((void**)&kin, g_kin);
    cudaGetSymbolAddress((void**)&vin, g_vin);
    cudaGetSymbolAddress((void**)&wt_hi, g_wt_hi);
    cudaGetSymbolAddress((void**)&wt_lo, g_wt_lo);
    cudaGetSymbolAddress((void**)&q16, g_q16);
    cudaGetSymbolAddress((void**)&k16, g_k16);
    cudaGetSymbolAddress((void**)&vbuf, g_v);
    cudaGetSymbolAddress((void**)&vt, g_vt);
    cudaGetSymbolAddress((void**)&ctx, g_ctx);

    // A fp16 single, B=W hi/lo 2-MMA:
    auto GP16 = gemm_mma<128, false, true, true,  true >;  // -> fp16 (q, k, ctx-like)
    auto GPF  = gemm_mma<128, false, true, false, true >;  // -> fp32 (vbuf, out)
    auto GS   = gemm_mma<128, false, false, false, false>; // scores: single/single
    auto GPV  = gemm_mma<64,  true,  false, true,  false>; // PV: split p, single v
    const int SM_PROJ = 2 * 1 * (128 * 80) + 2 * 2 * (128 * 80);  // 61440
    const int SM_SC   = 2 * 1 * (128 * 80) + 2 * 1 * (128 * 80);  // 40960
    const int SM_PV   = 2 * 2 * (128 * 80) + 2 * 1 * (64 * 80);   // 51200
    cudaFuncSetAttribute(GP16, cudaFuncAttributeMaxDynamicSharedMemorySize, SM_PROJ);
    cudaFuncSetAttribute(GPF,  cudaFuncAttributeMaxDynamicSharedMemorySize, SM_PROJ);
    cudaFuncSetAttribute(GS,   cudaFuncAttributeMaxDynamicSharedMemorySize, SM_SC);
    cudaFuncSetAttribute(GPV,  cudaFuncAttributeMaxDynamicSharedMemorySize, SM_PV);

    const long long SD  = (long long)S_ * D_;
    const long long SS  = (long long)S_ * S_;
    const long long HSS = (long long)H_ * SS;

    // 1) cast inputs to fp16
    const int ncast = (int)(NELEM / 1024);
    cast_kernel<<<ncast, 256>>>(query, qin);
    cast_kernel<<<ncast, 256>>>(key,   kin);
    cast_kernel<<<ncast, 256>>>(value, vin);

    // 2) transpose + split weights (fp16 hi/lo)
    const dim3 wtb(32, 8), wtg(32, 32);
    wtrans_kernel<<<wtg, wtb>>>(Wq, wt_hi + 0 * D_ * D_, wt_lo + 0 * D_ * D_);
    wtrans_kernel<<<wtg, wtb>>>(Wk, wt_hi + 1 * D_ * D_, wt_lo + 1 * D_ * D_);
    wtrans_kernel<<<wtg, wtb>>>(Wv, wt_hi + 2 * D_ * D_, wt_lo + 2 * D_ * D_);
    wtrans_kernel<<<wtg, wtb>>>(Wo, wt_hi + 3 * D_ * D_, wt_lo + 3 * D_ * D_);

    // 3) projections (Q folds the 0.125 scale)
    const dim3 gproj(D_ / 128, (B_ * S_) / 128, 1);
    GP16<<<gproj, 256, SM_PROJ>>>(qin, nullptr, wt_hi + 0 * D_ * D_, wt_lo + 0 * D_ * D_,
        bq, nullptr, q16, D_, D_, D_, D_, 1, 0, 0, 0, 0, 0, 0, 0.125f);
    GP16<<<gproj, 256, SM_PROJ>>>(kin, nullptr, wt_hi + 1 * D_ * D_, wt_lo + 1 * D_ * D_,
        bk, nullptr, k16, D_, D_, D_, D_, 1, 0, 0, 0, 0, 0, 0, 1.0f);
    GPF<<<gproj, 256, SM_PROJ>>>(vin, nullptr, wt_hi + 2 * D_ * D_, wt_lo + 2 * D_ * D_,
        bv, vbuf, nullptr, D_, D_, D_, D_, 1, 0, 0, 0, 0, 0, 0, 1.0f);

    // 4) transpose V -> vt [B*H, HD, S] fp16
    vtrans_kernel<<<dim3(S_ / 32, HD_ / 32, B_ * H_), wtb>>>(vbuf, vt);

    // 5) scores = q_scaled @ k^T -> attn fp32
    GS<<<dim3(S_ / 128, S_ / 128, B_ * H_), 256, SM_SC>>>(
        q16, nullptr, k16, nullptr, nullptr, attn, nullptr,
        HD_, D_, D_, S_, H_, SD, HD_, SD, HD_, HSS, SS, 1.0f);

    // 6) softmax in place
    softmax_rows<<<B_ * H_ * S_, 256>>>(attn);

    // 7) ctx = attn @ V  (attn fp32 split to hi/lo fp16 in-kernel; v single)
    GPV<<<dim3(1, S_ / 128, B_ * H_), 256, SM_PV>>>(
        nullptr, attn, vt, nullptr, nullptr, nullptr, ctx,
        S_, S_, S_, D_, H_, HSS, SS, (long long)HD_ * S_ * H_, (long long)HD_ * S_, SD, HD_, 1.0f);

    // 8) out = ctx @ Wo + bo
    GPF<<<gproj, 256, SM_PROJ>>>(ctx, nullptr, wt_hi + 3 * D_ * D_, wt_lo + 3 * D_ * D_,
        bo, out, nullptr, D_, D_, D_, D_, 1, 0, 0, 0, 0, 0, 0, 1.0f);
}

// round 6
// speedup vs baseline: 5.1038x; 1.4129x over previous
#include <cuda_runtime.h>
#include <cuda_fp16.h>
#include <cstdint>

#define B_ 2
#define S_ 2048
#define D_ 1024
#define H_ 16
#define HD_ 64

#define NELEM ((size_t)B_ * S_ * D_)

// ---------------- scratch (allocation-free contract) ----------------
__device__ __half g_qin[NELEM], g_kin[NELEM], g_vin[NELEM];
__device__ __half g_wt_hi[4 * D_ * D_], g_wt_lo[4 * D_ * D_];  // W^T [n][k] fp16 hi/lo
__device__ __half g_q16[NELEM], g_k16[NELEM];
__device__ float  g_v[NELEM];
__device__ __half g_vt[NELEM];      // [B*H, HD, S]
__device__ __half g_ctx[NELEM];
__device__ __half g_ps[(size_t)B_ * H_ * S_ * S_];      // p~ tiles, 268MB
__device__ float  g_mt[(size_t)B_ * H_ * 16 * 16 * 128]; // per (bh,rb,tile,row) running max
__device__ float2 g_fin[(size_t)B_ * H_ * 16 * 128];     // per (bh,rb,row): (m_final, 1/sum)

// ---------------- baseline-PTX helpers ----------------
__device__ __forceinline__ uint32_t smem_u32(const void* p) {
    uint32_t a;
    asm("{ .reg .u64 t; cvta.to.shared.u64 t, %1; cvt.u32.u64 %0, t; }" : "=r"(a) : "l"(p));
    return a;
}
#define CP_ASYNC16(dst, src) \
    asm volatile("cp.async.cg.shared.global [%0], [%1], 16;" :: "r"(dst), "l"(src))
#define CP_COMMIT() asm volatile("cp.async.commit_group;" ::: "memory")
#define CP_WAIT1()  asm volatile("cp.async.wait_group 1;" ::: "memory")
#define CP_WAIT0()  asm volatile("cp.async.wait_group 0;" ::: "memory")

#define LDMX4(r, a) \
    asm volatile("ldmatrix.sync.aligned.m8n8.x4.shared.b16 {%0,%1,%2,%3}, [%4];" \
        : "=r"((r)[0]), "=r"((r)[1]), "=r"((r)[2]), "=r"((r)[3]) : "r"(a))
#define LDMX2(r, a) \
    asm volatile("ldmatrix.sync.aligned.m8n8.x2.shared.b16 {%0,%1}, [%2];" \
        : "=r"((r)[0]), "=r"((r)[1]) : "r"(a))

#define MMA_F16(d, a, b) \
    asm volatile("mma.sync.aligned.m16n8k16.row.col.f32.f16.f16.f32 " \
        "{%0,%1,%2,%3},{%4,%5,%6,%7},{%8,%9},{%0,%1,%2,%3};" \
        : "+f"((d)[0]), "+f"((d)[1]), "+f"((d)[2]), "+f"((d)[3]) \
        : "r"((a)[0]), "r"((a)[1]), "r"((a)[2]), "r"((a)[3]), "r"((b)[0]), "r"((b)[1]))

// ---------------- fp32 -> fp16 cast ----------------
__global__ __launch_bounds__(256) void cast_kernel(
    const float* __restrict__ x, __half* __restrict__ y)
{
    size_t base = ((size_t)blockIdx.x * 256 + threadIdx.x) * 4;
    float4 v = *reinterpret_cast<const float4*>(x + base);
    alignas(8) __half h[4];
    h[0] = __float2half_rn(v.x); h[1] = __float2half_rn(v.y);
    h[2] = __float2half_rn(v.z); h[3] = __float2half_rn(v.w);
    *reinterpret_cast<uint2*>(y + base) = *reinterpret_cast<uint2*>(h);
}

// ---------------- weight transpose + fp16 hi/lo split ----------------
__global__ __launch_bounds__(256) void wtrans_kernel(
    const float* __restrict__ W, __half* __restrict__ th, __half* __restrict__ tl)
{
    __shared__ float t[32][33];
    const int tx = threadIdx.x, ty = threadIdx.y;
    const int n0 = blockIdx.x * 32, k0 = blockIdx.y * 32;
#pragma unroll
    for (int j = 0; j < 4; j++)
        t[ty + j * 8][tx] = W[(size_t)(k0 + ty + j * 8) * D_ + n0 + tx];
    __syncthreads();
#pragma unroll
    for (int j = 0; j < 4; j++) {
        float v = t[tx][ty + j * 8];
        __half h = __float2half_rn(v);
        __half l = __float2half_rn(v - __half2float(h));
        size_t o = (size_t)(n0 + ty + j * 8) * D_ + k0 + tx;
        th[o] = h; tl[o] = l;
    }
}

// ---------------- V transpose -> fp16: v[b,s,h*64+d] -> vt[(b*H+h)*64+d][s] ----------------
__global__ __launch_bounds__(256) void vtrans_kernel(
    const float* __restrict__ v, __half* __restrict__ th)
{
    __shared__ float t[32][33];
    const int tx = threadIdx.x, ty = threadIdx.y;
    const int s0 = blockIdx.x * 32, d0 = blockIdx.y * 32;
    const int z = blockIdx.z, b = z / H_, h = z % H_;
#pragma unroll
    for (int j = 0; j < 4; j++)
        t[ty + j * 8][tx] = v[(size_t)b * S_ * D_ + (size_t)(s0 + ty + j * 8) * D_ + h * HD_ + d0 + tx];
    __syncthreads();
#pragma unroll
    for (int j = 0; j < 4; j++) {
        size_t o = ((size_t)z * HD_ + d0 + ty + j * 8) * S_ + s0 + tx;
        th[o] = __float2half_rn(t[tx][ty + j * 8]);
    }
}

// ---------------- projection GEMM (fp16, W hi/lo 2-MMA) — as round 5 ----------------
template <int BN, bool BSPLIT, bool OUT16, bool HASBIAS>
__global__ __launch_bounds__(256, 1) void gemm_mma(
    const __half* __restrict__ A16,
    const __half* __restrict__ BhG, const __half* __restrict__ BlG,
    const float* __restrict__ bias,
    float* __restrict__ CfG, __half* __restrict__ C16G,
    int K, int lda, int ldb, int ldc, float scale)
{
    extern __shared__ char smem[];
    constexpr int AN = BN / 32;
    constexpr int BCOMP = BSPLIT ? 2 : 1;
    constexpr uint32_t A_STAGE = 128 * 80;
    constexpr uint32_t B_STAGE = BN * 80;
    constexpr uint32_t B_BASE = 2 * A_STAGE;
    const uint32_t sbase = smem_u32(smem);

    const int tid = threadIdx.x;
    const int wid = tid >> 5, lane = tid & 31;
    const int wm0 = (wid >> 2) * 64;
    const int wn0 = (wid & 3) * (BN / 4);
    const int row0 = blockIdx.y * 128, col0 = blockIdx.x * BN;

    float acc[4][AN][4];
#pragma unroll
    for (int im = 0; im < 4; im++)
#pragma unroll
        for (int in_ = 0; in_ < AN; in_++)
#pragma unroll
            for (int j = 0; j < 4; j++) acc[im][in_][j] = 0.0f;

    auto produce = [&](int i) {
        const int st = i & 1;
        const int k0 = i << 5;
#pragma unroll
        for (int c = tid; c < 512; c += 256) {
            int r = c >> 2, kc = c & 3;
            long long o = (long long)(row0 + r) * lda + k0 + kc * 8;
            CP_ASYNC16(sbase + st * A_STAGE + (uint32_t)(r * 80 + kc * 16), A16 + o);
        }
#pragma unroll
        for (int c = tid; c < BN * 4; c += 256) {
            int r = c >> 2, kc = c & 3;
            long long o = (long long)(col0 + r) * ldb + k0 + kc * 8;
            uint32_t d = sbase + B_BASE + (uint32_t)(r * 80 + kc * 16);
            CP_ASYNC16(d + st * BCOMP * B_STAGE, BhG + o);
            if (BSPLIT)
                CP_ASYNC16(d + (st * BCOMP + 1) * B_STAGE, BlG + o);
        }
        CP_COMMIT();
    };

    auto compute = [&](int st) {
        const uint32_t bAh = sbase + st * A_STAGE;
        const uint32_t bBh = sbase + B_BASE + st * BCOMP * B_STAGE;
        const uint32_t bBl = bBh + B_STAGE;
#pragma unroll
        for (int k2 = 0; k2 < 2; k2++) {
            uint32_t ah[4][4];
            const uint32_t ao = (uint32_t)((wm0 + (lane & 15)) * 80 +
                                           (k2 * 16 + (lane >> 4) * 8) * 2);
#pragma unroll
            for (int im = 0; im < 4; im++)
                LDMX4(ah[im], bAh + ao + im * (16 * 80));
            const uint32_t bo = (uint32_t)((wn0 + (lane & 7)) * 80 +
                                           (k2 * 16 + ((lane >> 3) & 1) * 8) * 2);
#pragma unroll
            for (int in_ = 0; in_ < AN; in_++) {
                uint32_t bh[2], bl[2];
                LDMX2(bh, bBh + bo + in_ * (8 * 80));
                if (BSPLIT) LDMX2(bl, bBl + bo + in_ * (8 * 80));
#pragma unroll
                for (int im = 0; im < 4; im++) {
                    MMA_F16(acc[im][in_], ah[im], bh);
                    if (BSPLIT) MMA_F16(acc[im][in_], ah[im], bl);
                }
            }
        }
    };

    const int NS = K >> 5;
    produce(0);
    produce(1);
    for (int i = 0; i < NS; i++) {
        if (i + 1 < NS) { CP_WAIT1(); } else { CP_WAIT0(); }
        __syncthreads();
        compute(i & 1);
        __syncthreads();
        if (i + 2 < NS) produce(i + 2);
    }

    const int qrow = lane >> 2;
    const int qcol = (lane & 3) * 2;
#pragma unroll
    for (int im = 0; im < 4; im++) {
#pragma unroll
        for (int half_ = 0; half_ < 2; half_++) {
            const int m = row0 + wm0 + im * 16 + qrow + half_ * 8;
#pragma unroll
            for (int in_ = 0; in_ < AN; in_++) {
                const int n = col0 + wn0 + in_ * 8 + qcol;
                float v0 = acc[im][in_][half_ * 2 + 0];
                float v1 = acc[im][in_][half_ * 2 + 1];
                if (HASBIAS) { v0 += bias[n]; v1 += bias[n + 1]; }
                v0 *= scale; v1 *= scale;
                const long long o = (long long)m * ldc + n;
                if (OUT16) {
                    __half2 hp = __floats2half2_rn(v0, v1);
                    *reinterpret_cast<uint32_t*>(C16G + o) = *reinterpret_cast<uint32_t*>(&hp);
                } else {
                    *reinterpret_cast<float2*>(CfG + o) = make_float2(v0, v1);
                }
            }
        }
    }
}

// ---------------- fused attention: scores + online softmax + PV ----------------
// grid (rb=S/128, bh=B*H). 8 warps; warp w owns q-rows [w*16, w*16+16).
// smem: QS 128x144B | KS 2x128x144B | VS 2x64x272B | PS 128x272B
__global__ __launch_bounds__(256, 1) void attn_fused(
    const __half* __restrict__ q16, const __half* __restrict__ k16,
    const __half* __restrict__ vt,
    __half* __restrict__ pscr, float* __restrict__ mt,
    float2* __restrict__ fin, __half* __restrict__ ctx)
{
    extern __shared__ char sm[];
    const uint32_t sb = smem_u32(sm);
    constexpr uint32_t QS = 0;
    constexpr uint32_t KS = 18432;
    constexpr uint32_t VS = 18432 + 36864;           // 55296
    constexpr uint32_t PS = 55296 + 34816;           // 90112
    const int tid = threadIdx.x, w = tid >> 5, lane = tid & 31;
    const int rb = blockIdx.x, bh = blockIdx.y, b = bh >> 4, h = bh & 15;
    const int lr = lane >> 2, lc = lane & 3;
    const int row0 = w * 16 + lr;

    // q tile (group 0)
    {
        const __half* src = q16 + ((size_t)b * S_ + (size_t)rb * 128) * D_ + h * 64;
        for (int c = tid; c < 1024; c += 256) {
            int r = c >> 3, ch = c & 7;
            CP_ASYNC16(sb + QS + r * 144 + ch * 16, src + (size_t)r * D_ + ch * 8);
        }
        CP_COMMIT();
    }
    auto produce = [&](int i) {
        int st = i & 1;
        const __half* ks = k16 + ((size_t)b * S_ + (size_t)i * 128) * D_ + h * 64;
        for (int c = tid; c < 1024; c += 256) {
            int r = c >> 3, ch = c & 7;
            CP_ASYNC16(sb + KS + st * 18432 + r * 144 + ch * 16, ks + (size_t)r * D_ + ch * 8);
        }
        const __half* vs = vt + ((size_t)bh * 64) * S_ + i * 128;
        for (int c = tid; c < 1024; c += 256) {
            int d = c >> 4, ch = c & 15;
            CP_ASYNC16(sb + VS + st * 17408 + d * 272 + ch * 16, vs + (size_t)d * S_ + ch * 8);
        }
        CP_COMMIT();
    };
    produce(0);
    produce(1);

    uint32_t qa[4][4];
    float ctxa[8][4];
#pragma unroll
    for (int f8 = 0; f8 < 8; f8++)
#pragma unroll
        for (int j = 0; j < 4; j++) ctxa[f8][j] = 0.0f;
    float m0 = -1e30f, m1 = -1e30f, sum0 = 0.0f, sum1 = 0.0f;

    for (int i = 0; i < 16; i++) {
        if (i + 1 < 16) { CP_WAIT1(); } else { CP_WAIT0(); }
        __syncthreads();
        if (i == 0) {
#pragma unroll
            for (int kc = 0; kc < 4; kc++)
                LDMX4(qa[kc], sb + QS + (w * 16 + (lane & 15)) * 144 +
                              (kc * 16 + (lane >> 4) * 8) * 2);
        }
        const uint32_t kbuf = sb + KS + (i & 1) * 18432;
        const uint32_t vbuf = sb + VS + (i & 1) * 17408;

        // s = q @ k^T, 16 n-frags of 8 cols
        float sa[16][4];
#pragma unroll
        for (int f = 0; f < 16; f++) {
            sa[f][0] = sa[f][1] = sa[f][2] = sa[f][3] = 0.0f;
        }
#pragma unroll
        for (int kc = 0; kc < 4; kc++) {
#pragma unroll
            for (int f = 0; f < 16; f++) {
                uint32_t kb[2];
                LDMX2(kb, kbuf + (f * 8 + (lane & 7)) * 144 +
                          (kc * 16 + ((lane >> 3) & 1) * 8) * 2);
                MMA_F16(sa[f], qa[kc], kb);
            }
        }

        // row max (quad shuffle)
        float mx0 = -1e30f, mx1 = -1e30f;
#pragma unroll
        for (int f = 0; f < 16; f++) {
            mx0 = fmaxf(mx0, fmaxf(sa[f][0], sa[f][1]));
            mx1 = fmaxf(mx1, fmaxf(sa[f][2], sa[f][3]));
        }
        mx0 = fmaxf(mx0, __shfl_xor_sync(0xffffffffu, mx0, 1));
        mx0 = fmaxf(mx0, __shfl_xor_sync(0xffffffffu, mx0, 2));
        mx1 = fmaxf(mx1, __shfl_xor_sync(0xffffffffu, mx1, 1));
        mx1 = fmaxf(mx1, __shfl_xor_sync(0xffffffffu, mx1, 2));
        float mn0 = fmaxf(m0, mx0), mn1 = fmaxf(m1, mx1);
        float sc0 = __expf(m0 - mn0), sc1 = __expf(m1 - mn1);

        // p~ = exp(s - mn), tile sums, fp16 pack
        uint32_t ph0[16], ph1[16];
        float ts0 = 0.0f, ts1 = 0.0f;
#pragma unroll
        for (int f = 0; f < 16; f++) {
            float p0 = __expf(sa[f][0] - mn0), p1 = __expf(sa[f][1] - mn0);
            float p2 = __expf(sa[f][2] - mn1), p3 = __expf(sa[f][3] - mn1);
            ts0 += p0 + p1; ts1 += p2 + p3;
            __half2 h01 = __floats2half2_rn(p0, p1);
            __half2 h23 = __floats2half2_rn(p2, p3);
            ph0[f] = *reinterpret_cast<uint32_t*>(&h01);
            ph1[f] = *reinterpret_cast<uint32_t*>(&h23);
        }
        ts0 += __shfl_xor_sync(0xffffffffu, ts0, 1);
        ts0 += __shfl_xor_sync(0xffffffffu, ts0, 2);
        ts1 += __shfl_xor_sync(0xffffffffu, ts1, 1);
        ts1 += __shfl_xor_sync(0xffffffffu, ts1, 2);
        sum0 = sum0 * sc0 + ts0;
        sum1 = sum1 * sc1 + ts1;
#pragma unroll
        for (int f8 = 0; f8 < 8; f8++) {
            ctxa[f8][0] *= sc0; ctxa[f8][1] *= sc0;
            ctxa[f8][2] *= sc1; ctxa[f8][3] *= sc1;
        }
        m0 = mn0; m1 = mn1;
        if (lc == 0) {
            float* mtp = mt + (((size_t)bh * 16 + rb) * 16 + i) * 128;
            mtp[row0] = mn0;
            mtp[row0 + 8] = mn1;
        }

        // ctx += p~ @ v   (A-frags from registers)
#pragma unroll
        for (int ks2 = 0; ks2 < 8; ks2++) {
            uint32_t pa[4] = { ph0[2 * ks2], ph1[2 * ks2],
                               ph0[2 * ks2 + 1], ph1[2 * ks2 + 1] };
#pragma unroll
            for (int f8 = 0; f8 < 8; f8++) {
                uint32_t vb[2];
                LDMX2(vb, vbuf + (f8 * 8 + (lane & 7)) * 272 +
                          (ks2 * 16 + ((lane >> 3) & 1) * 8) * 2);
                MMA_F16(ctxa[f8], pa, vb);
            }
        }

        // stage p~ to PS, then coalesced copy to gmem
#pragma unroll
        for (int f = 0; f < 16; f++) {
            *reinterpret_cast<uint32_t*>(sm + PS + row0 * 272 + f * 16 + lc * 4) = ph0[f];
            *reinterpret_cast<uint32_t*>(sm + PS + (row0 + 8) * 272 + f * 16 + lc * 4) = ph1[f];
        }
        __syncthreads();
        {
            __half* dst = pscr + ((((size_t)bh * 16 + rb) * 16 + i) << 14);
            for (int c = tid; c < 2048; c += 256) {
                int r = c >> 4, ch = c & 15;
                *reinterpret_cast<uint4*>(dst + r * 128 + ch * 8) =
                    *reinterpret_cast<uint4*>(sm + PS + r * 272 + ch * 16);
            }
        }
        __syncthreads();
        if (i + 2 < 16) produce(i + 2);
    }

    // finalize
    float inv0 = 1.0f / sum0, inv1 = 1.0f / sum1;
    if (lc == 0) {
        float2* fp = fin + ((size_t)bh * 16 + rb) * 128;
        fp[row0]     = make_float2(m0, inv0);
        fp[row0 + 8] = make_float2(m1, inv1);
    }
    // ctx -> QS staging -> gmem fp16
#pragma unroll
    for (int f8 = 0; f8 < 8; f8++) {
        __half2 c01 = __floats2half2_rn(ctxa[f8][0] * inv0, ctxa[f8][1] * inv0);
        __half2 c23 = __floats2half2_rn(ctxa[f8][2] * inv1, ctxa[f8][3] * inv1);
        *reinterpret_cast<uint32_t*>(sm + QS + row0 * 144 + f8 * 16 + lc * 4) =
            *reinterpret_cast<uint32_t*>(&c01);
        *reinterpret_cast<uint32_t*>(sm + QS + (row0 + 8) * 144 + f8 * 16 + lc * 4) =
            *reinterpret_cast<uint32_t*>(&c23);
    }
    __syncthreads();
    {
        __half* dst = ctx + ((size_t)b * S_ + (size_t)rb * 128) * D_ + h * 64;
        for (int c = tid; c < 1024; c += 256) {
            int r = c >> 3, ch = c & 7;
            *reinterpret_cast<uint4*>(dst + (size_t)r * D_ + ch * 8) =
                *reinterpret_cast<uint4*>(sm + QS + r * 144 + ch * 16);
        }
    }
}

// ---------------- rescale p~ -> normalized fp32 attn ----------------
__global__ __launch_bounds__(256) void attn_rescale(
    const __half* __restrict__ pscr, const float* __restrict__ mt,
    const float2* __restrict__ fin, float* __restrict__ attn)
{
    __shared__ float fac[16][128];
    const int blk = blockIdx.x;              // bh*16 + rb
    const int by  = blockIdx.y;              // row quarter
    const int bh = blk >> 4, rb = blk & 15;
    const int tid = threadIdx.x;
    if (tid < 128) {
        float2 f2 = fin[(size_t)blk * 128 + tid];
#pragma unroll
        for (int t = 0; t < 16; t++) {
            float mv = mt[((size_t)blk * 16 + t) * 128 + tid];
            fac[t][tid] = __expf(mv - f2.x) * f2.y;
        }
    }
    __syncthreads();
    const __half* src = pscr + ((size_t)blk << 18);
    float* dst = attn + ((size_t)bh * S_ + (size_t)rb * 128) * S_;
    const int ebase = by * 32 * 2048;
#pragma unroll 4
    for (int it = 0; it < 64; it++) {
        int e = ebase + (tid + it * 256) * 4;
        int r = e >> 11;
        int c = e & 2047;
        int t = c >> 7, tc = c & 127;
        uint2 pv = *reinterpret_cast<const uint2*>(src + ((size_t)t << 14) + r * 128 + tc);
        __half2 a  = *reinterpret_cast<__half2*>(&pv.x);
        __half2 b2 = *reinterpret_cast<__half2*>(&pv.y);
        float f = fac[t][r];
        float4 o;
        o.x = __half2float(a.x)  * f; o.y = __half2float(a.y)  * f;
        o.z = __half2float(b2.x) * f; o.w = __half2float(b2.y) * f;
        *reinterpret_cast<float4*>(dst + (size_t)r * S_ + c) = o;
    }
}

// ---------------- host ----------------
extern "C" void kernel_launch(void* const* d_in, const int* in_sizes, int n_in,
                              void* d_out, int out_size)
{
    const float* query = (const float*)d_in[0];
    const float* key   = (const float*)d_in[1];
    const float* value = (const float*)d_in[2];
    const float* Wq = (const float*)d_in[3];
    const float* bq = (const float*)d_in[4];
    const float* Wk = (const float*)d_in[5];
    const float* bk = (const float*)d_in[6];
    const float* Wv = (const float*)d_in[7];
    const float* bv = (const float*)d_in[8];
    const float* Wo = (const float*)d_in[9];
    const float* bo = (const float*)d_in[10];

    float* out  = (float*)d_out;
    float* attn = out + NELEM;

    __half *qin, *kin, *vin, *wt_hi, *wt_lo, *q16, *k16, *vt, *ctx, *ps;
    float *vbuf, *mtb;
    float2* finb;
    cudaGetSymbolAddress((void**)&qin, g_qin);
    cudaGetSymbolAddress((void**)&kin, g_kin);
    cudaGetSymbolAddress((void**)&vin, g_vin);
    cudaGetSymbolAddress((void**)&wt_hi, g_wt_hi);
    cudaGetSymbolAddress((void**)&wt_lo, g_wt_lo);
    cudaGetSymbolAddress((void**)&q16, g_q16);
    cudaGetSymbolAddress((void**)&k16, g_k16);
    cudaGetSymbolAddress((void**)&vbuf, g_v);
    cudaGetSymbolAddress((void**)&vt, g_vt);
    cudaGetSymbolAddress((void**)&ctx, g_ctx);
    cudaGetSymbolAddress((void**)&ps, g_ps);
    cudaGetSymbolAddress((void**)&mtb, g_mt);
    cudaGetSymbolAddress((void**)&finb, g_fin);

    auto GP16 = gemm_mma<128, true, true,  true>;   // -> fp16 (q, k)
    auto GPF  = gemm_mma<128, true, false, true>;   // -> fp32 (vbuf, out)
    const int SM_PROJ = 2 * (128 * 80) + 2 * 2 * (128 * 80);  // 61440
    cudaFuncSetAttribute(GP16, cudaFuncAttributeMaxDynamicSharedMemorySize, SM_PROJ);
    cudaFuncSetAttribute(GPF,  cudaFuncAttributeMaxDynamicSharedMemorySize, SM_PROJ);
    const int SM_ATTN = 124928;
    cudaFuncSetAttribute(attn_fused, cudaFuncAttributeMaxDynamicSharedMemorySize, SM_ATTN);

    // 1) cast inputs to fp16
    const int ncast = (int)(NELEM / 1024);
    cast_kernel<<<ncast, 256>>>(query, qin);
    cast_kernel<<<ncast, 256>>>(key,   kin);
    cast_kernel<<<ncast, 256>>>(value, vin);

    // 2) transpose + split weights (fp16 hi/lo)
    const dim3 wtb(32, 8), wtg(32, 32);
    wtrans_kernel<<<wtg, wtb>>>(Wq, wt_hi + 0 * D_ * D_, wt_lo + 0 * D_ * D_);
    wtrans_kernel<<<wtg, wtb>>>(Wk, wt_hi + 1 * D_ * D_, wt_lo + 1 * D_ * D_);
    wtrans_kernel<<<wtg, wtb>>>(Wv, wt_hi + 2 * D_ * D_, wt_lo + 2 * D_ * D_);
    wtrans_kernel<<<wtg, wtb>>>(Wo, wt_hi + 3 * D_ * D_, wt_lo + 3 * D_ * D_);

    // 3) projections (Q folds the 0.125 scale)
    const dim3 gproj(D_ / 128, (B_ * S_) / 128);
    GP16<<<gproj, 256, SM_PROJ>>>(qin, wt_hi + 0 * D_ * D_, wt_lo + 0 * D_ * D_,
        bq, nullptr, q16, D_, D_, D_, D_, 0.125f);
    GP16<<<gproj, 256, SM_PROJ>>>(kin, wt_hi + 1 * D_ * D_, wt_lo + 1 * D_ * D_,
        bk, nullptr, k16, D_, D_, D_, D_, 1.0f);
    GPF<<<gproj, 256, SM_PROJ>>>(vin, wt_hi + 2 * D_ * D_, wt_lo + 2 * D_ * D_,
        bv, vbuf, nullptr, D_, D_, D_, D_, 1.0f);

    // 4) transpose V -> vt [B*H, HD, S] fp16
    vtrans_kernel<<<dim3(S_ / 32, HD_ / 32, B_ * H_), wtb>>>(vbuf, vt);

    // 5) fused attention: p~ to scratch, ctx fp16, stats
    attn_fused<<<dim3(16, B_ * H_), 256, SM_ATTN>>>(q16, k16, vt, ps, mtb, finb, ctx);

    // 6) rescale p~ -> normalized fp32 attn
    attn_rescale<<<dim3(B_ * H_ * 16, 4), 256>>>(ps, mtb, finb, attn);

    // 7) out = ctx @ Wo + bo
    GPF<<<gproj, 256, SM_PROJ>>>(ctx, wt_hi + 3 * D_ * D_, wt_lo + 3 * D_ * D_,
        bo, out, nullptr, D_, D_, D_, D_, 1.0f);
}

// round 7
// speedup vs baseline: 6.8123x; 1.3348x over previous
#include <cuda_runtime.h>
#include <cuda_fp16.h>
#include <cstdint>

#define B_ 2
#define S_ 2048
#define D_ 1024
#define H_ 16
#define HD_ 64

#define NELEM ((size_t)B_ * S_ * D_)

// ---------------- scratch (allocation-free contract) ----------------
__device__ __half g_qin[NELEM], g_kin[NELEM], g_vin[NELEM];
__device__ __half g_wt[4 * D_ * D_];        // W^T [n][k] fp16
__device__ __half g_q16[NELEM], g_k16[NELEM], g_v16[NELEM];
__device__ __half g_vt[NELEM];              // [B*H, HD, S]
__device__ __half g_ctx[NELEM];
__device__ __half g_ps[(size_t)B_ * H_ * S_ * S_];       // p~ tiles
__device__ float  g_mt[(size_t)B_ * H_ * 16 * 16 * 128]; // per (bh,rb,tile,row) running max
__device__ float2 g_fin[(size_t)B_ * H_ * 16 * 128];     // per (bh,rb,row): (m_final, 1/sum)

// ---------------- baseline-PTX helpers ----------------
__device__ __forceinline__ uint32_t smem_u32(const void* p) {
    uint32_t a;
    asm("{ .reg .u64 t; cvta.to.shared.u64 t, %1; cvt.u32.u64 %0, t; }" : "=r"(a) : "l"(p));
    return a;
}
#define CP_ASYNC16(dst, src) \
    asm volatile("cp.async.cg.shared.global [%0], [%1], 16;" :: "r"(dst), "l"(src))
#define CP_COMMIT() asm volatile("cp.async.commit_group;" ::: "memory")
#define CP_WAIT1()  asm volatile("cp.async.wait_group 1;" ::: "memory")
#define CP_WAIT0()  asm volatile("cp.async.wait_group 0;" ::: "memory")

#define LDMX4(r, a) \
    asm volatile("ldmatrix.sync.aligned.m8n8.x4.shared.b16 {%0,%1,%2,%3}, [%4];" \
        : "=r"((r)[0]), "=r"((r)[1]), "=r"((r)[2]), "=r"((r)[3]) : "r"(a))
#define LDMX2(r, a) \
    asm volatile("ldmatrix.sync.aligned.m8n8.x2.shared.b16 {%0,%1}, [%2];" \
        : "=r"((r)[0]), "=r"((r)[1]) : "r"(a))

#define MMA_F16(d, a, b) \
    asm volatile("mma.sync.aligned.m16n8k16.row.col.f32.f16.f16.f32 " \
        "{%0,%1,%2,%3},{%4,%5,%6,%7},{%8,%9},{%0,%1,%2,%3};" \
        : "+f"((d)[0]), "+f"((d)[1]), "+f"((d)[2]), "+f"((d)[3]) \
        : "r"((a)[0]), "r"((a)[1]), "r"((a)[2]), "r"((a)[3]), "r"((b)[0]), "r"((b)[1]))

// ---------------- fp32 -> fp16 cast (3 tensors in one launch) ----------------
__global__ __launch_bounds__(256) void cast_kernel(
    const float* __restrict__ x0, const float* __restrict__ x1, const float* __restrict__ x2,
    __half* __restrict__ y0, __half* __restrict__ y1, __half* __restrict__ y2)
{
    const int z = blockIdx.y;
    const float* x = z == 0 ? x0 : (z == 1 ? x1 : x2);
    __half* y = z == 0 ? y0 : (z == 1 ? y1 : y2);
    size_t base = ((size_t)blockIdx.x * 256 + threadIdx.x) * 4;
    float4 v = *reinterpret_cast<const float4*>(x + base);
    alignas(8) __half h[4];
    h[0] = __float2half_rn(v.x); h[1] = __float2half_rn(v.y);
    h[2] = __float2half_rn(v.z); h[3] = __float2half_rn(v.w);
    *reinterpret_cast<uint2*>(y + base) = *reinterpret_cast<uint2*>(h);
}

// ---------------- weight transpose -> fp16: W[k][n] -> Wt[n][k] ----------------
__global__ __launch_bounds__(256) void wtrans_kernel(
    const float* __restrict__ W0, const float* __restrict__ W1,
    const float* __restrict__ W2, const float* __restrict__ W3,
    __half* __restrict__ th)
{
    __shared__ float t[32][33];
    const int tx = threadIdx.x, ty = threadIdx.y;
    const int n0 = blockIdx.x * 32, k0 = blockIdx.y * 32;
    const int z = blockIdx.z;
    const float* W = z == 0 ? W0 : (z == 1 ? W1 : (z == 2 ? W2 : W3));
    __half* dst = th + (size_t)z * D_ * D_;
#pragma unroll
    for (int j = 0; j < 4; j++)
        t[ty + j * 8][tx] = W[(size_t)(k0 + ty + j * 8) * D_ + n0 + tx];
    __syncthreads();
#pragma unroll
    for (int j = 0; j < 4; j++)
        dst[(size_t)(n0 + ty + j * 8) * D_ + k0 + tx] = __float2half_rn(t[tx][ty + j * 8]);
}

// ---------------- V transpose -> fp16: v[b,s,h*64+d] -> vt[(b*H+h)*64+d][s] ----------------
__global__ __launch_bounds__(256) void vtrans_kernel(
    const __half* __restrict__ v, __half* __restrict__ th)
{
    __shared__ __half t[32][40];
    const int tx = threadIdx.x, ty = threadIdx.y;
    const int s0 = blockIdx.x * 32, d0 = blockIdx.y * 32;
    const int z = blockIdx.z, b = z / H_, h = z % H_;
#pragma unroll
    for (int j = 0; j < 4; j++)
        t[ty + j * 8][tx] = v[(size_t)b * S_ * D_ + (size_t)(s0 + ty + j * 8) * D_ + h * HD_ + d0 + tx];
    __syncthreads();
#pragma unroll
    for (int j = 0; j < 4; j++) {
        size_t o = ((size_t)z * HD_ + d0 + ty + j * 8) * S_ + s0 + tx;
        th[o] = t[tx][ty + j * 8];
    }
}

// ---------------- projection GEMM (fp16 single-MMA) ----------------
// grid (N/128, M/128, nz). z selects A/bias/C (QKV fused launch).
// C[m,n] = scale_z * (sum_k A[m,k] * W^T[n,k] + bias[n])
template <bool OUT16>
__global__ __launch_bounds__(256, 2) void gemm_proj(
    const __half* __restrict__ A0, const __half* __restrict__ A1, const __half* __restrict__ A2,
    const __half* __restrict__ Wt,   // base; + z*D*D
    const float* __restrict__ b0, const float* __restrict__ b1, const float* __restrict__ b2,
    float* __restrict__ Cf,
    __half* __restrict__ C0, __half* __restrict__ C1, __half* __restrict__ C2,
    float scale0)
{
    extern __shared__ char smem[];
    constexpr uint32_t A_STAGE = 128 * 80;
    constexpr uint32_t B_BASE = 2 * A_STAGE;
    const uint32_t sbase = smem_u32(smem);

    const int tid = threadIdx.x;
    const int wid = tid >> 5, lane = tid & 31;
    const int wm0 = (wid >> 2) * 64;
    const int wn0 = (wid & 3) * 32;
    const int row0 = blockIdx.y * 128, col0 = blockIdx.x * 128;

    const int z = blockIdx.z;
    const __half* A    = z == 0 ? A0 : (z == 1 ? A1 : A2);
    const float*  bias = z == 0 ? b0 : (z == 1 ? b1 : b2);
    __half* C16 = z == 0 ? C0 : (z == 1 ? C1 : C2);
    const float scale = z == 0 ? scale0 : 1.0f;
    const __half* W = Wt + (size_t)z * D_ * D_;

    float acc[4][4][4];
#pragma unroll
    for (int im = 0; im < 4; im++)
#pragma unroll
        for (int in_ = 0; in_ < 4; in_++)
#pragma unroll
            for (int j = 0; j < 4; j++) acc[im][in_][j] = 0.0f;

    auto produce = [&](int i) {
        const int st = i & 1;
        const int k0 = i << 5;
#pragma unroll
        for (int c = tid; c < 512; c += 256) {
            int r = c >> 2, kc = c & 3;
            CP_ASYNC16(sbase + st * A_STAGE + (uint32_t)(r * 80 + kc * 16),
                       A + (long long)(row0 + r) * D_ + k0 + kc * 8);
        }
#pragma unroll
        for (int c = tid; c < 512; c += 256) {
            int r = c >> 2, kc = c & 3;
            CP_ASYNC16(sbase + B_BASE + st * A_STAGE + (uint32_t)(r * 80 + kc * 16),
                       W + (long long)(col0 + r) * D_ + k0 + kc * 8);
        }
        CP_COMMIT();
    };

    auto compute = [&](int st) {
        const uint32_t bA = sbase + st * A_STAGE;
        const uint32_t bB = sbase + B_BASE + st * A_STAGE;
#pragma unroll
        for (int k2 = 0; k2 < 2; k2++) {
            uint32_t ah[4][4];
            const uint32_t ao = (uint32_t)((wm0 + (lane & 15)) * 80 +
                                           (k2 * 16 + (lane >> 4) * 8) * 2);
#pragma unroll
            for (int im = 0; im < 4; im++)
                LDMX4(ah[im], bA + ao + im * (16 * 80));
            const uint32_t bo = (uint32_t)((wn0 + (lane & 7)) * 80 +
                                           (k2 * 16 + ((lane >> 3) & 1) * 8) * 2);
#pragma unroll
            for (int in_ = 0; in_ < 4; in_++) {
                uint32_t bh[2];
                LDMX2(bh, bB + bo + in_ * (8 * 80));
#pragma unroll
                for (int im = 0; im < 4; im++)
                    MMA_F16(acc[im][in_], ah[im], bh);
            }
        }
    };

    const int NS = D_ >> 5;
    produce(0);
    produce(1);
    for (int i = 0; i < NS; i++) {
        if (i + 1 < NS) { CP_WAIT1(); } else { CP_WAIT0(); }
        __syncthreads();
        compute(i & 1);
        __syncthreads();
        if (i + 2 < NS) produce(i + 2);
    }

    const int qrow = lane >> 2;
    const int qcol = (lane & 3) * 2;
#pragma unroll
    for (int im = 0; im < 4; im++) {
#pragma unroll
        for (int half_ = 0; half_ < 2; half_++) {
            const int m = row0 + wm0 + im * 16 + qrow + half_ * 8;
#pragma unroll
            for (int in_ = 0; in_ < 4; in_++) {
                const int n = col0 + wn0 + in_ * 8 + qcol;
                float v0 = (acc[im][in_][half_ * 2 + 0] + bias[n])     * scale;
                float v1 = (acc[im][in_][half_ * 2 + 1] + bias[n + 1]) * scale;
                const long long o = (long long)m * D_ + n;
                if (OUT16) {
                    __half2 hp = __floats2half2_rn(v0, v1);
                    *reinterpret_cast<uint32_t*>(C16 + o) = *reinterpret_cast<uint32_t*>(&hp);
                } else {
                    *reinterpret_cast<float2*>(Cf + o) = make_float2(v0, v1);
                }
            }
        }
    }
}

// ---------------- fused attention: scores + online softmax + PV ----------------
// grid (rb=S/128, bh=B*H). 8 warps; warp w owns q-rows [w*16, w*16+16).
// smem: QS 128x144B | KS 2x128x144B | VS 2x64x272B | PS 128x272B
__global__ __launch_bounds__(256, 1) void attn_fused(
    const __half* __restrict__ q16, const __half* __restrict__ k16,
    const __half* __restrict__ vt,
    __half* __restrict__ pscr, float* __restrict__ mt,
    float2* __restrict__ fin, __half* __restrict__ ctx)
{
    extern __shared__ char sm[];
    const uint32_t sb = smem_u32(sm);
    constexpr uint32_t QS = 0;
    constexpr uint32_t KS = 18432;
    constexpr uint32_t VS = 18432 + 36864;           // 55296
    constexpr uint32_t PS = 55296 + 34816;           // 90112
    const int tid = threadIdx.x, w = tid >> 5, lane = tid & 31;
    const int rb = blockIdx.x, bh = blockIdx.y, b = bh >> 4, h = bh & 15;
    const int lr = lane >> 2, lc = lane & 3;
    const int row0 = w * 16 + lr;

    // q tile (group 0)
    {
        const __half* src = q16 + ((size_t)b * S_ + (size_t)rb * 128) * D_ + h * 64;
        for (int c = tid; c < 1024; c += 256) {
            int r = c >> 3, ch = c & 7;
            CP_ASYNC16(sb + QS + r * 144 + ch * 16, src + (size_t)r * D_ + ch * 8);
        }
        CP_COMMIT();
    }
    auto produce = [&](int i) {
        int st = i & 1;
        const __half* ks = k16 + ((size_t)b * S_ + (size_t)i * 128) * D_ + h * 64;
        for (int c = tid; c < 1024; c += 256) {
            int r = c >> 3, ch = c & 7;
            CP_ASYNC16(sb + KS + st * 18432 + r * 144 + ch * 16, ks + (size_t)r * D_ + ch * 8);
        }
        const __half* vs = vt + ((size_t)bh * 64) * S_ + i * 128;
        for (int c = tid; c < 1024; c += 256) {
            int d = c >> 4, ch = c & 15;
            CP_ASYNC16(sb + VS + st * 17408 + d * 272 + ch * 16, vs + (size_t)d * S_ + ch * 8);
        }
        CP_COMMIT();
    };
    produce(0);
    produce(1);

    uint32_t qa[4][4];
    float ctxa[8][4];
#pragma unroll
    for (int f8 = 0; f8 < 8; f8++)
#pragma unroll
        for (int j = 0; j < 4; j++) ctxa[f8][j] = 0.0f;
    float m0 = -1e30f, m1 = -1e30f, sum0 = 0.0f, sum1 = 0.0f;

    for (int i = 0; i < 16; i++) {
        if (i + 1 < 16) { CP_WAIT1(); } else { CP_WAIT0(); }
        __syncthreads();
        if (i == 0) {
#pragma unroll
            for (int kc = 0; kc < 4; kc++)
                LDMX4(qa[kc], sb + QS + (w * 16 + (lane & 15)) * 144 +
                              (kc * 16 + (lane >> 4) * 8) * 2);
        }
        const uint32_t kbuf = sb + KS + (i & 1) * 18432;
        const uint32_t vbuf = sb + VS + (i & 1) * 17408;

        // s = q @ k^T, 16 n-frags of 8 cols
        float sa[16][4];
#pragma unroll
        for (int f = 0; f < 16; f++) {
            sa[f][0] = sa[f][1] = sa[f][2] = sa[f][3] = 0.0f;
        }
#pragma unroll
        for (int kc = 0; kc < 4; kc++) {
#pragma unroll
            for (int f = 0; f < 16; f++) {
                uint32_t kb[2];
                LDMX2(kb, kbuf + (f * 8 + (lane & 7)) * 144 +
                          (kc * 16 + ((lane >> 3) & 1) * 8) * 2);
                MMA_F16(sa[f], qa[kc], kb);
            }
        }

        // row max (quad shuffle)
        float mx0 = -1e30f, mx1 = -1e30f;
#pragma unroll
        for (int f = 0; f < 16; f++) {
            mx0 = fmaxf(mx0, fmaxf(sa[f][0], sa[f][1]));
            mx1 = fmaxf(mx1, fmaxf(sa[f][2], sa[f][3]));
        }
        mx0 = fmaxf(mx0, __shfl_xor_sync(0xffffffffu, mx0, 1));
        mx0 = fmaxf(mx0, __shfl_xor_sync(0xffffffffu, mx0, 2));
        mx1 = fmaxf(mx1, __shfl_xor_sync(0xffffffffu, mx1, 1));
        mx1 = fmaxf(mx1, __shfl_xor_sync(0xffffffffu, mx1, 2));
        float mn0 = fmaxf(m0, mx0), mn1 = fmaxf(m1, mx1);
        float sc0 = __expf(m0 - mn0), sc1 = __expf(m1 - mn1);

        // p~ = exp(s - mn), tile sums, fp16 pack
        uint32_t ph0[16], ph1[16];
        float ts0 = 0.0f, ts1 = 0.0f;
#pragma unroll
        for (int f = 0; f < 16; f++) {
            float p0 = __expf(sa[f][0] - mn0), p1 = __expf(sa[f][1] - mn0);
            float p2 = __expf(sa[f][2] - mn1), p3 = __expf(sa[f][3] - mn1);
            ts0 += p0 + p1; ts1 += p2 + p3;
            __half2 h01 = __floats2half2_rn(p0, p1);
            __half2 h23 = __floats2half2_rn(p2, p3);
            ph0[f] = *reinterpret_cast<uint32_t*>(&h01);
            ph1[f] = *reinterpret_cast<uint32_t*>(&h23);
        }
        ts0 += __shfl_xor_sync(0xffffffffu, ts0, 1);
        ts0 += __shfl_xor_sync(0xffffffffu, ts0, 2);
        ts1 += __shfl_xor_sync(0xffffffffu, ts1, 1);
        ts1 += __shfl_xor_sync(0xffffffffu, ts1, 2);
        sum0 = sum0 * sc0 + ts0;
        sum1 = sum1 * sc1 + ts1;
#pragma unroll
        for (int f8 = 0; f8 < 8; f8++) {
            ctxa[f8][0] *= sc0; ctxa[f8][1] *= sc0;
            ctxa[f8][2] *= sc1; ctxa[f8][3] *= sc1;
        }
        m0 = mn0; m1 = mn1;
        if (lc == 0) {
            float* mtp = mt + (((size_t)bh * 16 + rb) * 16 + i) * 128;
            mtp[row0] = mn0;
            mtp[row0 + 8] = mn1;
        }

        // ctx += p~ @ v   (A-frags from registers)
#pragma unroll
        for (int ks2 = 0; ks2 < 8; ks2++) {
            uint32_t pa[4] = { ph0[2 * ks2], ph1[2 * ks2],
                               ph0[2 * ks2 + 1], ph1[2 * ks2 + 1] };
#pragma unroll
            for (int f8 = 0; f8 < 8; f8++) {
                uint32_t vb[2];
                LDMX2(vb, vbuf + (f8 * 8 + (lane & 7)) * 272 +
                          (ks2 * 16 + ((lane >> 3) & 1) * 8) * 2);
                MMA_F16(ctxa[f8], pa, vb);
            }
        }

        // stage p~ to PS, then coalesced copy to gmem
#pragma unroll
        for (int f = 0; f < 16; f++) {
            *reinterpret_cast<uint32_t*>(sm + PS + row0 * 272 + f * 16 + lc * 4) = ph0[f];
            *reinterpret_cast<uint32_t*>(sm + PS + (row0 + 8) * 272 + f * 16 + lc * 4) = ph1[f];
        }
        __syncthreads();
        {
            __half* dst = pscr + ((((size_t)bh * 16 + rb) * 16 + i) << 14);
            for (int c = tid; c < 2048; c += 256) {
                int r = c >> 4, ch = c & 15;
                *reinterpret_cast<uint4*>(dst + r * 128 + ch * 8) =
                    *reinterpret_cast<uint4*>(sm + PS + r * 272 + ch * 16);
            }
        }
        __syncthreads();
        if (i + 2 < 16) produce(i + 2);
    }

    // finalize
    float inv0 = 1.0f / sum0, inv1 = 1.0f / sum1;
    if (lc == 0) {
        float2* fp = fin + ((size_t)bh * 16 + rb) * 128;
        fp[row0]     = make_float2(m0, inv0);
        fp[row0 + 8] = make_float2(m1, inv1);
    }
    // ctx -> QS staging -> gmem fp16
#pragma unroll
    for (int f8 = 0; f8 < 8; f8++) {
        __half2 c01 = __floats2half2_rn(ctxa[f8][0] * inv0, ctxa[f8][1] * inv0);
        __half2 c23 = __floats2half2_rn(ctxa[f8][2] * inv1, ctxa[f8][3] * inv1);
        *reinterpret_cast<uint32_t*>(sm + QS + row0 * 144 + f8 * 16 + lc * 4) =
            *reinterpret_cast<uint32_t*>(&c01);
        *reinterpret_cast<uint32_t*>(sm + QS + (row0 + 8) * 144 + f8 * 16 + lc * 4) =
            *reinterpret_cast<uint32_t*>(&c23);
    }
    __syncthreads();
    {
        __half* dst = ctx + ((size_t)b * S_ + (size_t)rb * 128) * D_ + h * 64;
        for (int c = tid; c < 1024; c += 256) {
            int r = c >> 3, ch = c & 7;
            *reinterpret_cast<uint4*>(dst + (size_t)r * D_ + ch * 8) =
                *reinterpret_cast<uint4*>(sm + QS + r * 144 + ch * 16);
        }
    }
}

// ---------------- rescale p~ -> normalized fp32 attn ----------------
__global__ __launch_bounds__(256) void attn_rescale(
    const __half* __restrict__ pscr, const float* __restrict__ mt,
    const float2* __restrict__ fin, float* __restrict__ attn)
{
    __shared__ float fac[16][128];
    const int blk = blockIdx.x;              // bh*16 + rb
    const int by  = blockIdx.y;              // row quarter
    const int bh = blk >> 4, rb = blk & 15;
    const int tid = threadIdx.x;
    if (tid < 128) {
        float2 f2 = fin[(size_t)blk * 128 + tid];
#pragma unroll
        for (int t = 0; t < 16; t++) {
            float mv = mt[((size_t)blk * 16 + t) * 128 + tid];
            fac[t][tid] = __expf(mv - f2.x) * f2.y;
        }
    }
    __syncthreads();
    const __half* src = pscr + ((size_t)blk << 18);
    float* dst = attn + ((size_t)bh * S_ + (size_t)rb * 128) * S_;
    const int ebase = by * 32 * 2048;
#pragma unroll 4
    for (int it = 0; it < 64; it++) {
        int e = ebase + (tid + it * 256) * 4;
        int r = e >> 11;
        int c = e & 2047;
        int t = c >> 7, tc = c & 127;
        uint2 pv = *reinterpret_cast<const uint2*>(src + ((size_t)t << 14) + r * 128 + tc);
        __half2 a  = *reinterpret_cast<__half2*>(&pv.x);
        __half2 b2 = *reinterpret_cast<__half2*>(&pv.y);
        float f = fac[t][r];
        float4 o;
        o.x = __half2float(a.x)  * f; o.y = __half2float(a.y)  * f;
        o.z = __half2float(b2.x) * f; o.w = __half2float(b2.y) * f;
        *reinterpret_cast<float4*>(dst + (size_t)r * S_ + c) = o;
    }
}

// ---------------- host ----------------
extern "C" void kernel_launch(void* const* d_in, const int* in_sizes, int n_in,
                              void* d_out, int out_size)
{
    const float* query = (const float*)d_in[0];
    const float* key   = (const float*)d_in[1];
    const float* value = (const float*)d_in[2];
    const float* Wq = (const float*)d_in[3];
    const float* bq = (const float*)d_in[4];
    const float* Wk = (const float*)d_in[5];
    const float* bk = (const float*)d_in[6];
    const float* Wv = (const float*)d_in[7];
    const float* bv = (const float*)d_in[8];
    const float* Wo = (const float*)d_in[9];
    const float* bo = (const float*)d_in[10];

    float* out  = (float*)d_out;
    float* attn = out + NELEM;

    __half *qin, *kin, *vin, *wt, *q16, *k16, *v16, *vt, *ctx, *ps;
    float* mtb;
    float2* finb;
    cudaGetSymbolAddress((void**)&qin, g_qin);
    cudaGetSymbolAddress((void**)&kin, g_kin);
    cudaGetSymbolAddress((void**)&vin, g_vin);
    cudaGetSymbolAddress((void**)&wt, g_wt);
    cudaGetSymbolAddress((void**)&q16, g_q16);
    cudaGetSymbolAddress((void**)&k16, g_k16);
    cudaGetSymbolAddress((void**)&v16, g_v16);
    cudaGetSymbolAddress((void**)&vt, g_vt);
    cudaGetSymbolAddress((void**)&ctx, g_ctx);
    cudaGetSymbolAddress((void**)&ps, g_ps);
    cudaGetSymbolAddress((void**)&mtb, g_mt);
    cudaGetSymbolAddress((void**)&finb, g_fin);

    auto GP16 = gemm_proj<true>;    // QKV fused -> fp16
    auto GPF  = gemm_proj<false>;   // out proj -> fp32
    const int SM_PROJ = 4 * 128 * 80;   // 40960
    cudaFuncSetAttribute(GP16, cudaFuncAttributeMaxDynamicSharedMemorySize, SM_PROJ);
    cudaFuncSetAttribute(GPF,  cudaFuncAttributeMaxDynamicSharedMemorySize, SM_PROJ);
    const int SM_ATTN = 124928;
    cudaFuncSetAttribute(attn_fused, cudaFuncAttributeMaxDynamicSharedMemorySize, SM_ATTN);

    // 1) cast q,k,v inputs to fp16 (one launch)
    cast_kernel<<<dim3((unsigned)(NELEM / 1024), 3), 256>>>(query, key, value, qin, kin, vin);

    // 2) transpose weights -> fp16 W^T (one launch, z = which W)
    wtrans_kernel<<<dim3(32, 32, 4), dim3(32, 8)>>>(Wq, Wk, Wv, Wo, wt);

    // 3) QKV projections in one launch (z selects); Q folds 0.125
    gemm_proj<true><<<dim3(D_ / 128, (B_ * S_) / 128, 3), 256, SM_PROJ>>>(
        qin, kin, vin, wt, bq, bk, bv, nullptr, q16, k16, v16, 0.125f);

    // 4) transpose V -> vt [B*H, HD, S]
    vtrans_kernel<<<dim3(S_ / 32, HD_ / 32, B_ * H_), dim3(32, 8)>>>(v16, vt);

    // 5) fused attention: p~ to scratch, ctx fp16, stats
    attn_fused<<<dim3(16, B_ * H_), 256, SM_ATTN>>>(q16, k16, vt, ps, mtb, finb, ctx);

    // 6) rescale p~ -> normalized fp32 attn
    attn_rescale<<<dim3(B_ * H_ * 16, 4), 256>>>(ps, mtb, finb, attn);

    // 7) out = ctx @ Wo + bo
    gemm_proj<false><<<dim3(D_ / 128, (B_ * S_) / 128, 1), 256, SM_PROJ>>>(
        ctx, nullptr, nullptr, wt + 3 * D_ * D_, bo, nullptr, nullptr,
        out, nullptr, nullptr, nullptr, 1.0f);
}